// round 9
// baseline (speedup 1.0000x reference)
#include <cuda_runtime.h>
#include <cuda_bf16.h>
#include <cuda_fp16.h>
#include <math.h>
#include <stdint.h>

// ---------------- problem constants ----------------
#define S_LEN   1024
#define D_MODEL 5120
#define H_HEADS 128
#define Q_LORA  1536
#define KV_LORA 512
#define ROPE_D  64
#define NOPE_D  128
#define VDIM    128
#define Q_HEAD  192
#define LATENT  576
#define QBN     24576
#define OUTW    16384

typedef __nv_bfloat16 bf16;
typedef __half fp16;

// ---------------- scratch (device globals; no allocation) ----------------
__device__ __align__(16) bf16 g_h2    [(size_t)S_LEN * 3 * D_MODEL];
__device__ __align__(16) bf16 g_qaw2  [(size_t)3 * D_MODEL * Q_LORA];
__device__ __align__(16) bf16 g_qa2   [(size_t)S_LEN * 3 * Q_LORA];
__device__ __align__(16) bf16 g_qbw2  [(size_t)3 * Q_LORA * QBN];
__device__ __align__(16) bf16 g_qn2   [(size_t)H_HEADS * S_LEN * 3 * NOPE_D];
__device__ __align__(16) bf16 g_kc2   [(size_t)H_HEADS * 3 * NOPE_D * KV_LORA];
__device__ __align__(16) bf16 g_kvaw2 [(size_t)3 * D_MODEL * LATENT];
__device__ __align__(16) bf16 g_lat2  [(size_t)S_LEN * 3 * KV_LORA];
__device__ __align__(16) bf16 g_kT2   [(size_t)3 * LATENT * S_LEN];
__device__ __align__(16) bf16 g_vc2   [(size_t)H_HEADS * 3 * KV_LORA * VDIM];
__device__ __align__(16) bf16 g_qfull2[(size_t)H_HEADS * S_LEN * 3 * LATENT];
// veffH[h]: (2*S, VDIM) fp16, rows 2k and 2k+1 both = fp16(V_eff[k])
__device__ __align__(16) fp16 g_veffH [(size_t)H_HEADS * 2 * S_LEN * VDIM];
// probsH[h][q]: K-interleaved fp16 pairs (hi,lo) -> width 2*S
__device__ __align__(16) fp16 g_probsH[(size_t)H_HEADS * S_LEN * 2 * S_LEN];
// bigoH: (S, 2*OUTW) fp16 A-style [hi | lo]
__device__ __align__(16) fp16 g_bigoH [(size_t)S_LEN * 2 * OUTW];
// owH: (2*OUTW, D_MODEL) fp16, rows k and OUTW+k both = fp16(o_w[k])
__device__ __align__(16) fp16 g_owH   [(size_t)2 * OUTW * D_MODEL];
// fp32 intermediates
__device__ __align__(16) float g_qa   [(size_t)S_LEN * Q_LORA];
__device__ __align__(16) float g_q    [(size_t)S_LEN * QBN];
__device__ __align__(16) float g_kv   [(size_t)S_LEN * LATENT];
__device__ __align__(16) float g_kfull[(size_t)S_LEN * LATENT];
__device__ __align__(16) float g_scores[(size_t)H_HEADS * S_LEN * S_LEN];

// ---------------- PTX helpers ----------------
__device__ __forceinline__ void cp_async16(uint32_t dst, const void* src, bool pred) {
    int sz = pred ? 16 : 0;
    asm volatile("cp.async.cg.shared.global [%0], [%1], 16, %2;\n"
                 :: "r"(dst), "l"(src), "r"(sz));
}
__device__ __forceinline__ void cp_commit() {
    asm volatile("cp.async.commit_group;\n" ::: "memory");
}
__device__ __forceinline__ void ldsm_x4(uint32_t* r, uint32_t addr) {
    asm volatile("ldmatrix.sync.aligned.m8n8.x4.shared.b16 {%0,%1,%2,%3}, [%4];\n"
                 : "=r"(r[0]), "=r"(r[1]), "=r"(r[2]), "=r"(r[3]) : "r"(addr));
}
__device__ __forceinline__ void ldsm_x4_t(uint32_t* r, uint32_t addr) {
    asm volatile("ldmatrix.sync.aligned.m8n8.x4.trans.shared.b16 {%0,%1,%2,%3}, [%4];\n"
                 : "=r"(r[0]), "=r"(r[1]), "=r"(r[2]), "=r"(r[3]) : "r"(addr));
}
__device__ __forceinline__ void mma_bf16(float* d, const uint32_t* a, const uint32_t* b) {
    asm volatile("mma.sync.aligned.m16n8k16.row.col.f32.bf16.bf16.f32 "
                 "{%0,%1,%2,%3},{%4,%5,%6,%7},{%8,%9},{%0,%1,%2,%3};\n"
                 : "+f"(d[0]), "+f"(d[1]), "+f"(d[2]), "+f"(d[3])
                 : "r"(a[0]), "r"(a[1]), "r"(a[2]), "r"(a[3]), "r"(b[0]), "r"(b[1]));
}
__device__ __forceinline__ void mma_fp16(float* d, const uint32_t* a, const uint32_t* b) {
    asm volatile("mma.sync.aligned.m16n8k16.row.col.f32.f16.f16.f32 "
                 "{%0,%1,%2,%3},{%4,%5,%6,%7},{%8,%9},{%0,%1,%2,%3};\n"
                 : "+f"(d[0]), "+f"(d[1]), "+f"(d[2]), "+f"(d[3])
                 : "r"(a[0]), "r"(a[1]), "r"(a[2]), "r"(a[3]), "r"(b[0]), "r"(b[1]));
}

__device__ __forceinline__ void split_bf16(float x, bf16& hi, bf16& lo) {
    hi = __float2bfloat16(x);
    lo = __float2bfloat16(x - __bfloat162float(hi));
}
__device__ __forceinline__ void split_fp16(float x, fp16& hi, fp16& lo) {
    hi = __float2half(x);
    lo = __float2half(x - __half2float(hi));
}

// ---------------- templated tensor-core GEMM: 128x128x64, 3-stage ----------------
// EPI: 0 = fp32 C * alpha
//      1 = bf16 splitA [hi|hi|lo] (off2 = copy distance)
//      3 = fp16 dup-row interleave: rows 2m and 2m+1 both = fp16(v)   (V_eff)
//      4 = fp16 2-term A-style [hi|lo] (off2 = copy distance)          (bigout)
// TRI: lower-triangular tile launch
// KLIM: 0 off, else Keff = min(K, KLIM*(m0+BM))
// FP16: operands are fp16 (else bf16)
#define BM 128
#define BN 128
#define BK 64
#define ASTR (BK + 8)
#define BSTR (BN + 8)
#define NSTG 3
#define A_STG (BM * ASTR)
#define B_STG (BK * BSTR)
#define SMEM_ELEMS (NSTG * (A_STG + B_STG))
#define SMEM_BYTES (SMEM_ELEMS * 2)

template<int EPI, int TRI, int KLIM, int FP16>
__global__ void __launch_bounds__(256, 2) gemm_t(
    const bf16* __restrict__ A, const bf16* __restrict__ B, void* __restrict__ Cv,
    int M, int N, int K, int lda, int ldb, int ldc,
    long sA, long sB, long sC, float alpha, int off2)
{
    extern __shared__ bf16 smem[];
    bf16 (*As)[BM][ASTR] = (bf16(*)[BM][ASTR])smem;
    bf16 (*Bs)[BK][BSTR] = (bf16(*)[BK][BSTR])(smem + NSTG * A_STG);

    int tm, tn;
    if (TRI) {
        int x = blockIdx.x;
        int r = (int)((-1.f + sqrtf(1.f + 8.f * (float)x)) * 0.5f);
        while ((r + 1) * (r + 2) / 2 <= x) ++r;
        while (r * (r + 1) / 2 > x) --r;
        tm = r; tn = x - r * (r + 1) / 2;
    } else { tn = blockIdx.x; tm = blockIdx.y; }

    const int m0 = tm * BM;
    const int n0 = tn * BN;
    A += (long)blockIdx.z * sA;
    B += (long)blockIdx.z * sB;

    int Keff = K;
    if (KLIM) { int lim = KLIM * (m0 + BM); Keff = (lim < K) ? lim : K; }

    const int tid  = threadIdx.x;
    const int lane = tid & 31;
    const int warp = tid >> 5;
    const int wm   = warp >> 1;
    const int wn   = warp & 1;

    float acc[2][8][4];
#pragma unroll
    for (int a = 0; a < 2; a++)
#pragma unroll
        for (int b = 0; b < 8; b++)
#pragma unroll
            for (int c = 0; c < 4; c++) acc[a][b][c] = 0.f;

    const int ktiles = Keff / BK;

    auto load_tiles = [&](int buf, int kt) {
#pragma unroll
        for (int i = 0; i < 4; i++) {
            int seg = tid + 256 * i;
            int r = seg >> 3, c = (seg & 7) * 8;
            uint32_t dst = (uint32_t)__cvta_generic_to_shared(&As[buf][r][c]);
            cp_async16(dst, A + (long)(m0 + r) * lda + kt + c, true);
        }
#pragma unroll
        for (int i = 0; i < 4; i++) {
            int seg = tid + 256 * i;
            int r = seg >> 4, c = (seg & 15) * 8;
            uint32_t dst = (uint32_t)__cvta_generic_to_shared(&Bs[buf][r][c]);
            bool ok = (n0 + c) < N;
            const bf16* src = ok ? (B + (long)(kt + r) * ldb + n0 + c) : B;
            cp_async16(dst, src, ok);
        }
        cp_commit();
    };

    load_tiles(0, 0);
    if (ktiles > 1) load_tiles(1, BK);

    for (int t = 0; t < ktiles; t++) {
        const int buf = t % NSTG;
        if (t + 2 < ktiles) {
            load_tiles((t + 2) % NSTG, (t + 2) * BK);
            asm volatile("cp.async.wait_group 2;" ::: "memory");
        } else if (t + 1 < ktiles) {
            asm volatile("cp.async.wait_group 1;" ::: "memory");
        } else {
            asm volatile("cp.async.wait_group 0;" ::: "memory");
        }
        __syncthreads();

#pragma unroll
        for (int kk = 0; kk < 4; kk++) {
            uint32_t af[2][4];
#pragma unroll
            for (int mt = 0; mt < 2; mt++) {
                uint32_t addr = (uint32_t)__cvta_generic_to_shared(
                    &As[buf][wm * 32 + mt * 16 + (lane & 15)][kk * 16 + (lane >> 4) * 8]);
                ldsm_x4(af[mt], addr);
            }
            uint32_t bfr[4][4];
#pragma unroll
            for (int np = 0; np < 4; np++) {
                uint32_t addr = (uint32_t)__cvta_generic_to_shared(
                    &Bs[buf][kk * 16 + (lane & 15)][wn * 64 + np * 16 + (lane >> 4) * 8]);
                ldsm_x4_t(bfr[np], addr);
            }
#pragma unroll
            for (int mt = 0; mt < 2; mt++)
#pragma unroll
                for (int nt = 0; nt < 8; nt++) {
                    if (FP16) mma_fp16(acc[mt][nt], af[mt], &bfr[nt >> 1][(nt & 1) * 2]);
                    else      mma_bf16(acc[mt][nt], af[mt], &bfr[nt >> 1][(nt & 1) * 2]);
                }
        }
        __syncthreads();
    }

    // ---- epilogue ----
    const int r  = lane >> 2;
    const int c2 = (lane & 3) * 2;

    auto emit = [&](int m, int n, float v0, float v1) {
        v0 *= alpha; v1 *= alpha;
        if (EPI == 0) {
            float* C = (float*)Cv + (long)blockIdx.z * sC;
            C[(long)m * ldc + n]     = v0;
            C[(long)m * ldc + n + 1] = v1;
        } else if (EPI == 1) {
            bf16* C = (bf16*)Cv + (long)blockIdx.z * sC;
            bf16 h0, l0, h1, l1;
            split_bf16(v0, h0, l0); split_bf16(v1, h1, l1);
            __nv_bfloat162 hi2 = __nv_bfloat162(h0, h1);
            __nv_bfloat162 lo2 = __nv_bfloat162(l0, l1);
            long base = (long)m * ldc + n;
            *(__nv_bfloat162*)&C[base] = hi2;
            *(__nv_bfloat162*)&C[base + off2] = hi2;
            *(__nv_bfloat162*)&C[base + 2 * off2] = lo2;
        } else if (EPI == 3) {
            fp16* C = (fp16*)Cv + (long)blockIdx.z * sC;
            __half2 h2 = __floats2half2_rn(v0, v1);
            *(__half2*)&C[(long)(2 * m)     * ldc + n] = h2;
            *(__half2*)&C[(long)(2 * m + 1) * ldc + n] = h2;
        } else {
            fp16* C = (fp16*)Cv + (long)blockIdx.z * sC;
            fp16 h0, l0, h1, l1;
            split_fp16(v0, h0, l0); split_fp16(v1, h1, l1);
            __half2 hi2 = __half2(h0, h1);
            __half2 lo2 = __half2(l0, l1);
            long base = (long)m * ldc + n;
            *(__half2*)&C[base] = hi2;
            *(__half2*)&C[base + off2] = lo2;
        }
    };

#pragma unroll
    for (int mt = 0; mt < 2; mt++) {
#pragma unroll
        for (int nt = 0; nt < 8; nt++) {
            int m = m0 + wm * 32 + mt * 16 + r;
            int n = n0 + wn * 64 + nt * 8 + c2;
            if (n < N) {
                emit(m,     n, acc[mt][nt][0], acc[mt][nt][1]);
                emit(m + 8, n, acc[mt][nt][2], acc[mt][nt][3]);
            }
        }
    }
}

// ---------------- vectorized converters ----------------
union BV4 { bf16 b[4]; uint2 u; };
union HV4 { fp16 h[4]; uint2 u; };

__global__ void convA4_k(const float* __restrict__ src, bf16* __restrict__ dst,
                         int M, int K, int lda, long ssrc)
{
    src += (long)blockIdx.z * ssrc;
    dst += (long)blockIdx.z * M * 3 * K;
    int K4 = K >> 2;
    long total = (long)M * K4;
    for (long idx = (long)blockIdx.x * blockDim.x + threadIdx.x; idx < total;
         idx += (long)gridDim.x * blockDim.x) {
        int m = (int)(idx / K4), k = (int)(idx % K4) * 4;
        float4 x = *(const float4*)(src + (long)m * lda + k);
        BV4 hv, lv;
        split_bf16(x.x, hv.b[0], lv.b[0]);
        split_bf16(x.y, hv.b[1], lv.b[1]);
        split_bf16(x.z, hv.b[2], lv.b[2]);
        split_bf16(x.w, hv.b[3], lv.b[3]);
        bf16* row = dst + (long)m * 3 * K;
        *(uint2*)&row[k]         = hv.u;
        *(uint2*)&row[K + k]     = hv.u;
        *(uint2*)&row[2 * K + k] = lv.u;
    }
}

__global__ void convB4_k(const float* __restrict__ src, bf16* __restrict__ dst,
                         int K, int N, int ldb, long ssrc)
{
    src += (long)blockIdx.z * ssrc;
    dst += (long)blockIdx.z * 3 * K * N;
    int N4 = N >> 2;
    long total = (long)K * N4;
    for (long idx = (long)blockIdx.x * blockDim.x + threadIdx.x; idx < total;
         idx += (long)gridDim.x * blockDim.x) {
        int k = (int)(idx / N4), n = (int)(idx % N4) * 4;
        float4 x = *(const float4*)(src + (long)k * ldb + n);
        BV4 hv, lv;
        split_bf16(x.x, hv.b[0], lv.b[0]);
        split_bf16(x.y, hv.b[1], lv.b[1]);
        split_bf16(x.z, hv.b[2], lv.b[2]);
        split_bf16(x.w, hv.b[3], lv.b[3]);
        *(uint2*)&dst[(long)k * N + n]           = hv.u;
        *(uint2*)&dst[((long)K + k) * N + n]     = lv.u;
        *(uint2*)&dst[((long)2 * K + k) * N + n] = hv.u;
    }
}

// fp16 hi-only, duplicated rows: src (K x N fp32) -> dst (2K x N fp16), rows k and K+k = fp16(x)
__global__ void convBh_k(const float* __restrict__ src, fp16* __restrict__ dst,
                         int K, int N, int ldb)
{
    int N4 = N >> 2;
    long total = (long)K * N4;
    for (long idx = (long)blockIdx.x * blockDim.x + threadIdx.x; idx < total;
         idx += (long)gridDim.x * blockDim.x) {
        int k = (int)(idx / N4), n = (int)(idx % N4) * 4;
        float4 x = *(const float4*)(src + (long)k * ldb + n);
        HV4 hv;
        hv.h[0] = __float2half(x.x);
        hv.h[1] = __float2half(x.y);
        hv.h[2] = __float2half(x.z);
        hv.h[3] = __float2half(x.w);
        *(uint2*)&dst[(long)k * N + n]       = hv.u;
        *(uint2*)&dst[((long)K + k) * N + n] = hv.u;
    }
}

__global__ void convBt_k(const float* __restrict__ src, bf16* __restrict__ dst,
                         int K, int N, int lds)
{
    long total = (long)K * N;
    for (long idx = (long)blockIdx.x * blockDim.x + threadIdx.x; idx < total;
         idx += (long)gridDim.x * blockDim.x) {
        int k = (int)(idx / N), n = (int)(idx % N);
        float x = src[(long)n * lds + k];
        bf16 hi, lo; split_bf16(x, hi, lo);
        dst[(long)k * N + n] = hi;
        dst[((long)K + k) * N + n] = lo;
        dst[((long)2 * K + k) * N + n] = hi;
    }
}

// ---------------- elementwise kernels ----------------
__global__ void rmsnorm_rows_k(float* x, const float* __restrict__ w, int W)
{
    int row = blockIdx.x;
    float* p = x + (long)row * W;
    __shared__ float red[256];
    int tid = threadIdx.x;
    float ss = 0.f;
    for (int i = tid; i < W; i += 256) { float v = p[i]; ss += v * v; }
    red[tid] = ss; __syncthreads();
    for (int st = 128; st > 0; st >>= 1) {
        if (tid < st) red[tid] += red[tid + st];
        __syncthreads();
    }
    float r = rsqrtf(red[0] / (float)W + 1e-6f);
    for (int i = tid; i < W; i += 256) p[i] = p[i] * r * w[i];
}

__global__ void build_kfull_k(const float* __restrict__ kv, const float* __restrict__ lnw,
                              const float* __restrict__ cosb, const float* __restrict__ sinb,
                              float* __restrict__ kfull)
{
    int s = blockIdx.x;
    int tid = threadIdx.x;
    const float* row = kv + (long)s * LATENT;
    float* out = kfull + (long)s * LATENT;
    __shared__ float red[256];
    float ss = 0.f;
    for (int i = tid; i < KV_LORA; i += 256) { float v = row[i]; ss += v * v; }
    red[tid] = ss; __syncthreads();
    for (int st = 128; st > 0; st >>= 1) {
        if (tid < st) red[tid] += red[tid + st];
        __syncthreads();
    }
    float r = rsqrtf(red[0] / (float)KV_LORA + 1e-6f);
    for (int i = tid; i < KV_LORA; i += 256) out[i] = row[i] * r * lnw[i];
    if (tid < ROPE_D) {
        int j = tid;
        float x = row[KV_LORA + j];
        float rot = (j < 32) ? -row[KV_LORA + j + 32] : row[KV_LORA + j - 32];
        out[KV_LORA + j] = x * cosb[s * ROPE_D + j] + rot * sinb[s * ROPE_D + j];
    }
}

__global__ void rope_qpe2_k(const float* __restrict__ q,
                            const float* __restrict__ cosb, const float* __restrict__ sinb,
                            bf16* __restrict__ qfull2)
{
    int s = blockIdx.x;
    int h = blockIdx.y;
    int j = threadIdx.x;
    const float* x = q + (long)s * QBN + h * Q_HEAD + NOPE_D;
    float v = x[j];
    float rot = (j < 32) ? -x[j + 32] : x[j - 32];
    float val = v * cosb[s * ROPE_D + j] + rot * sinb[s * ROPE_D + j];
    bf16 hi, lo; split_bf16(val, hi, lo);
    bf16* row = qfull2 + ((long)h * S_LEN + s) * (3 * LATENT);
    row[KV_LORA + j] = hi;
    row[LATENT + KV_LORA + j] = hi;
    row[2 * LATENT + KV_LORA + j] = lo;
}

// causal softmax -> fp16 (hi,lo) K-interleaved pairs, width 2*S
__global__ void softmax_probsH_k(const float* __restrict__ scores, fp16* __restrict__ probsH)
{
    int q = blockIdx.x;
    int h = blockIdx.y;
    int tid = threadIdx.x;
    const float* row = scores + ((long)h * S_LEN + q) * S_LEN;
    fp16* orow = probsH + ((long)h * S_LEN + q) * (2 * S_LEN);
    int n = q + 1;
    int imax = ((q >> 7) + 1) << 7;
    __shared__ float red[256];

    int i0 = tid * 4;
    bool act = i0 < imax;
    float a[4] = {0.f, 0.f, 0.f, 0.f};
    if (act) { float4 v = *(const float4*)(row + i0); a[0]=v.x; a[1]=v.y; a[2]=v.z; a[3]=v.w; }

    float mx = -3.4e38f;
#pragma unroll
    for (int j = 0; j < 4; j++)
        if (i0 + j < n) mx = fmaxf(mx, a[j]);
    red[tid] = mx; __syncthreads();
    for (int st = 128; st > 0; st >>= 1) {
        if (tid < st) red[tid] = fmaxf(red[tid], red[tid + st]);
        __syncthreads();
    }
    mx = red[0];
    __syncthreads();

    float sum = 0.f;
#pragma unroll
    for (int j = 0; j < 4; j++) {
        a[j] = (i0 + j < n) ? __expf(a[j] - mx) : 0.f;
        sum += a[j];
    }
    red[tid] = sum; __syncthreads();
    for (int st = 128; st > 0; st >>= 1) {
        if (tid < st) red[tid] += red[tid + st];
        __syncthreads();
    }
    float inv = 1.f / red[0];

    if (act) {
        __align__(16) fp16 buf[8];
#pragma unroll
        for (int j = 0; j < 4; j++) {
            float p = a[j] * inv;
            fp16 hi, lo; split_fp16(p, hi, lo);
            buf[2 * j + 0] = hi;
            buf[2 * j + 1] = lo;
        }
        *(uint4*)(orow + 2 * i0) = *(const uint4*)buf;
    }
}

// ---------------- host-side launchers ----------------
template<int EPI, int TRI, int KLIM, int FP16>
static void gemm(const void* A, const void* B, void* C,
                 int M, int N, int K, int lda, int ldb, int ldc,
                 long sA, long sB, long sC, int batch, float alpha, int off2)
{
    cudaFuncSetAttribute(gemm_t<EPI, TRI, KLIM, FP16>,
                         cudaFuncAttributeMaxDynamicSharedMemorySize, SMEM_BYTES);
    dim3 grid;
    if (TRI) {
        int t = M / BM;
        grid = dim3(t * (t + 1) / 2, 1, batch);
    } else {
        grid = dim3((N + BN - 1) / BN, M / BM, batch);
    }
    gemm_t<EPI, TRI, KLIM, FP16><<<grid, 256, SMEM_BYTES>>>(
        (const bf16*)A, (const bf16*)B, C, M, N, K, lda, ldb, ldc, sA, sB, sC, alpha, off2);
}
static void convA(const float* src, bf16* dst, int M, int K, int lda, long ssrc, int batch)
{
    long total = (long)M * (K >> 2);
    int blocks = (int)((total + 255) / 256);
    if (blocks > 2048) blocks = 2048;
    convA4_k<<<dim3(blocks, 1, batch), 256>>>(src, dst, M, K, lda, ssrc);
}
static void convB(const float* src, bf16* dst, int K, int N, int ldb, long ssrc, int batch)
{
    long total = (long)K * (N >> 2);
    int blocks = (int)((total + 255) / 256);
    if (blocks > 2048) blocks = 2048;
    convB4_k<<<dim3(blocks, 1, batch), 256>>>(src, dst, K, N, ldb, ssrc);
}

extern "C" void kernel_launch(void* const* d_in, const int* in_sizes, int n_in,
                              void* d_out, int out_size)
{
    const float* h      = (const float*)d_in[0];
    const float* cosb   = (const float*)d_in[1];
    const float* sinb   = (const float*)d_in[2];
    const float* q_a_w  = (const float*)d_in[3];
    const float* q_a_ln = (const float*)d_in[4];
    const float* q_b_w  = (const float*)d_in[5];
    const float* kv_a_w = (const float*)d_in[6];
    const float* kv_ln  = (const float*)d_in[7];
    const float* kc_w   = (const float*)d_in[8];
    const float* vc_w   = (const float*)d_in[9];
    const float* o_w    = (const float*)d_in[10];
    float* out = (float*)d_out;

    bf16 *p_h2, *p_qaw2, *p_qa2, *p_qbw2, *p_qn2, *p_kc2, *p_kvaw2, *p_lat2, *p_kT2;
    bf16 *p_vc2, *p_qfull2;
    fp16 *p_veffH, *p_probsH, *p_bigoH, *p_owH;
    float *p_qa, *p_q, *p_kv, *p_kfull, *p_scores;
    cudaGetSymbolAddress((void**)&p_h2,     g_h2);
    cudaGetSymbolAddress((void**)&p_qaw2,   g_qaw2);
    cudaGetSymbolAddress((void**)&p_qa2,    g_qa2);
    cudaGetSymbolAddress((void**)&p_qbw2,   g_qbw2);
    cudaGetSymbolAddress((void**)&p_qn2,    g_qn2);
    cudaGetSymbolAddress((void**)&p_kc2,    g_kc2);
    cudaGetSymbolAddress((void**)&p_kvaw2,  g_kvaw2);
    cudaGetSymbolAddress((void**)&p_lat2,   g_lat2);
    cudaGetSymbolAddress((void**)&p_kT2,    g_kT2);
    cudaGetSymbolAddress((void**)&p_vc2,    g_vc2);
    cudaGetSymbolAddress((void**)&p_qfull2, g_qfull2);
    cudaGetSymbolAddress((void**)&p_veffH,  g_veffH);
    cudaGetSymbolAddress((void**)&p_probsH, g_probsH);
    cudaGetSymbolAddress((void**)&p_bigoH,  g_bigoH);
    cudaGetSymbolAddress((void**)&p_owH,    g_owH);
    cudaGetSymbolAddress((void**)&p_qa,     g_qa);
    cudaGetSymbolAddress((void**)&p_q,      g_q);
    cudaGetSymbolAddress((void**)&p_kv,     g_kv);
    cudaGetSymbolAddress((void**)&p_kfull,  g_kfull);
    cudaGetSymbolAddress((void**)&p_scores, g_scores);

    double mscale = 0.1 * log(40.0) + 1.0;
    const float SCALE = (float)(pow((double)Q_HEAD, -0.5) * mscale * mscale);

    // ---- conversions ----
    convA(h,      p_h2,    S_LEN, D_MODEL, D_MODEL, 0, 1);
    convB(q_a_w,  p_qaw2,  D_MODEL, Q_LORA, Q_LORA, 0, 1);
    convB(kv_a_w, p_kvaw2, D_MODEL, LATENT, LATENT, 0, 1);
    convB(q_b_w,  p_qbw2,  Q_LORA, QBN, QBN, 0, 1);
    convB(kc_w,   p_kc2,   NOPE_D, KV_LORA, KV_LORA, (long)NOPE_D * KV_LORA, H_HEADS);
    convB(vc_w,   p_vc2,   KV_LORA, VDIM, VDIM, (long)KV_LORA * VDIM, H_HEADS);
    {   // o_w -> fp16 hi duplicated (2*OUTW x D_MODEL)
        long total = (long)OUTW * (D_MODEL >> 2);
        int blocks = (int)((total + 255) / 256);
        if (blocks > 2048) blocks = 2048;
        convBh_k<<<blocks, 256>>>(o_w, p_owH, OUTW, D_MODEL, D_MODEL);
    }

    // 1) qa = h @ q_a_w
    gemm<0,0,0,0>(p_h2, p_qaw2, p_qa, S_LEN, Q_LORA, 3 * D_MODEL,
                  3 * D_MODEL, Q_LORA, Q_LORA, 0, 0, 0, 1, 1.f, 0);
    // 2) rmsnorm + split
    rmsnorm_rows_k<<<S_LEN, 256>>>(p_qa, q_a_ln, Q_LORA);
    convA(p_qa, p_qa2, S_LEN, Q_LORA, Q_LORA, 0, 1);
    // 3) q = qa_n @ q_b_w
    gemm<0,0,0,0>(p_qa2, p_qbw2, p_q, S_LEN, QBN, 3 * Q_LORA,
                  3 * Q_LORA, QBN, QBN, 0, 0, 0, 1, 1.f, 0);
    // 4) kv = h @ kv_a_w
    gemm<0,0,0,0>(p_h2, p_kvaw2, p_kv, S_LEN, LATENT, 3 * D_MODEL,
                  3 * D_MODEL, LATENT, LATENT, 0, 0, 0, 1, 1.f, 0);
    // 5) k_full; split latent (A-style) + transposed k_full (B-style)
    build_kfull_k<<<S_LEN, 256>>>(p_kv, kv_ln, cosb, sinb, p_kfull);
    convA(p_kfull, p_lat2, S_LEN, KV_LORA, LATENT, 0, 1);
    {
        long total = (long)LATENT * S_LEN;
        int blocks = (int)((total + 255) / 256);
        convBt_k<<<blocks, 256>>>(p_kfull, p_kT2, LATENT, S_LEN, LATENT);
    }
    // 6) q_nope slices -> split; q_full[:, :512] fused splitA epilogue
    convA(p_q, p_qn2, S_LEN, NOPE_D, QBN, (long)Q_HEAD, H_HEADS);
    gemm<1,0,0,0>(p_qn2, p_kc2, p_qfull2,
                  S_LEN, KV_LORA, 3 * NOPE_D,
                  3 * NOPE_D, KV_LORA, 3 * LATENT,
                  (long)S_LEN * 3 * NOPE_D, (long)3 * NOPE_D * KV_LORA,
                  (long)S_LEN * 3 * LATENT, H_HEADS, 1.f, LATENT);
    // 7) rope(q_pe)
    {
        dim3 grid(S_LEN, H_HEADS);
        rope_qpe2_k<<<grid, 64>>>(p_q, cosb, sinb, p_qfull2);
    }
    // 8) V_eff[h] = latent @ vc_w[h] (bf16 3-term), fp16 dup-row epilogue
    gemm<3,0,0,0>(p_lat2, p_vc2, p_veffH,
                  S_LEN, VDIM, 3 * KV_LORA,
                  3 * KV_LORA, VDIM, VDIM,
                  0, (long)3 * KV_LORA * VDIM, (long)2 * S_LEN * VDIM,
                  H_HEADS, 1.f, 0);
    // 9) scores (lower-triangle tiles only, bf16 3-term)
    gemm<0,1,0,0>(p_qfull2, p_kT2, p_scores,
                  S_LEN, S_LEN, 3 * LATENT,
                  3 * LATENT, S_LEN, S_LEN,
                  (long)S_LEN * 3 * LATENT, 0, (long)S_LEN * S_LEN,
                  H_HEADS, SCALE, 0);
    // 10) causal softmax -> fp16 (hi,lo) pairs
    {
        dim3 grid(S_LEN, H_HEADS);
        softmax_probsH_k<<<grid, 256>>>(p_scores, p_probsH);
    }
    // 11) big_out = probs @ V_eff  (fp16 2-term, causal K-limit x2, fp16 [hi|lo] epilogue)
    gemm<4,0,2,1>(p_probsH, p_veffH, p_bigoH,
                  S_LEN, VDIM, 2 * S_LEN,
                  2 * S_LEN, VDIM, 2 * OUTW,
                  (long)S_LEN * 2 * S_LEN, (long)2 * S_LEN * VDIM, (long)VDIM,
                  H_HEADS, 1.f, OUTW);
    // 12) out = big_out @ o_w  (fp16 2-term)
    gemm<0,0,0,1>(p_bigoH, p_owH, out, S_LEN, D_MODEL, 2 * OUTW,
                  2 * OUTW, D_MODEL, D_MODEL, 0, 0, 0, 1, 1.f, 0);
}

// round 11
// speedup vs baseline: 1.3857x; 1.3857x over previous
#include <cuda_runtime.h>
#include <cuda_bf16.h>
#include <math.h>
#include <stdint.h>

// ---------------- problem constants ----------------
#define S_LEN   1024
#define D_MODEL 5120
#define H_HEADS 128
#define Q_LORA  1536
#define KV_LORA 512
#define ROPE_D  64
#define NOPE_D  128
#define VDIM    128
#define Q_HEAD  192
#define LATENT  576
#define QBN     24576
#define OUTW    16384

typedef __nv_bfloat16 bf16;

// ---------------- scratch (device globals; no allocation) ----------------
__device__ __align__(16) bf16 g_h2    [(size_t)S_LEN * 3 * D_MODEL];
__device__ __align__(16) bf16 g_qaw2  [(size_t)3 * D_MODEL * Q_LORA];
__device__ __align__(16) bf16 g_qa2   [(size_t)S_LEN * 3 * Q_LORA];
__device__ __align__(16) bf16 g_qbw2  [(size_t)3 * Q_LORA * QBN];
__device__ __align__(16) bf16 g_qn2   [(size_t)H_HEADS * S_LEN * 3 * NOPE_D];
__device__ __align__(16) bf16 g_kc2   [(size_t)H_HEADS * 3 * NOPE_D * KV_LORA];
__device__ __align__(16) bf16 g_kvaw2 [(size_t)3 * D_MODEL * LATENT];
__device__ __align__(16) bf16 g_lat2  [(size_t)S_LEN * 3 * KV_LORA];
__device__ __align__(16) bf16 g_kT2   [(size_t)3 * LATENT * S_LEN];
__device__ __align__(16) bf16 g_vc2   [(size_t)H_HEADS * 3 * KV_LORA * VDIM];
__device__ __align__(16) bf16 g_qfull2[(size_t)H_HEADS * S_LEN * 3 * LATENT];
__device__ __align__(16) bf16 g_veff2 [(size_t)H_HEADS * 3 * S_LEN * VDIM];
__device__ __align__(16) bf16 g_probs2[(size_t)H_HEADS * S_LEN * 3 * S_LEN];
__device__ __align__(16) bf16 g_bigo2 [(size_t)S_LEN * 3 * OUTW];
__device__ __align__(16) bf16 g_ow2   [(size_t)3 * OUTW * D_MODEL];
// fp32 intermediates
__device__ __align__(16) float g_qa   [(size_t)S_LEN * Q_LORA];
__device__ __align__(16) float g_q    [(size_t)S_LEN * QBN];
__device__ __align__(16) float g_kv   [(size_t)S_LEN * LATENT];
__device__ __align__(16) float g_kfull[(size_t)S_LEN * LATENT];
__device__ __align__(16) float g_scores[(size_t)H_HEADS * S_LEN * S_LEN];

// ---------------- PTX helpers ----------------
__device__ __forceinline__ void cp_async16(uint32_t dst, const void* src, bool pred) {
    int sz = pred ? 16 : 0;
    asm volatile("cp.async.cg.shared.global [%0], [%1], 16, %2;\n"
                 :: "r"(dst), "l"(src), "r"(sz));
}
__device__ __forceinline__ void cp_commit() {
    asm volatile("cp.async.commit_group;\n" ::: "memory");
}
__device__ __forceinline__ void ldsm_x4(uint32_t* r, uint32_t addr) {
    asm volatile("ldmatrix.sync.aligned.m8n8.x4.shared.b16 {%0,%1,%2,%3}, [%4];\n"
                 : "=r"(r[0]), "=r"(r[1]), "=r"(r[2]), "=r"(r[3]) : "r"(addr));
}
__device__ __forceinline__ void ldsm_x4_t(uint32_t* r, uint32_t addr) {
    asm volatile("ldmatrix.sync.aligned.m8n8.x4.trans.shared.b16 {%0,%1,%2,%3}, [%4];\n"
                 : "=r"(r[0]), "=r"(r[1]), "=r"(r[2]), "=r"(r[3]) : "r"(addr));
}
__device__ __forceinline__ void mma_bf16(float* d, const uint32_t* a, const uint32_t* b) {
    asm volatile("mma.sync.aligned.m16n8k16.row.col.f32.bf16.bf16.f32 "
                 "{%0,%1,%2,%3},{%4,%5,%6,%7},{%8,%9},{%0,%1,%2,%3};\n"
                 : "+f"(d[0]), "+f"(d[1]), "+f"(d[2]), "+f"(d[3])
                 : "r"(a[0]), "r"(a[1]), "r"(a[2]), "r"(a[3]), "r"(b[0]), "r"(b[1]));
}

__device__ __forceinline__ void split_bf16(float x, bf16& hi, bf16& lo) {
    hi = __float2bfloat16(x);
    lo = __float2bfloat16(x - __bfloat162float(hi));
}

// ---------------- templated bf16 tensor-core GEMM: 128x128x64, 3-stage ----------------
#define BM 128
#define BN 128
#define BK 64
#define ASTR (BK + 8)
#define BSTR (BN + 8)
#define NSTG 3
#define A_STG (BM * ASTR)
#define B_STG (BK * BSTR)
#define SMEM_ELEMS (NSTG * (A_STG + B_STG))
#define SMEM_BYTES (SMEM_ELEMS * 2)

template<int EPI, int TRI, int KLIM>
__global__ void __launch_bounds__(256, 2) gemm_t(
    const bf16* __restrict__ A, const bf16* __restrict__ B, void* __restrict__ Cv,
    int M, int N, int K, int lda, int ldb, int ldc,
    long sA, long sB, long sC, float alpha, int off2)
{
    extern __shared__ bf16 smem[];
    bf16 (*As)[BM][ASTR] = (bf16(*)[BM][ASTR])smem;
    bf16 (*Bs)[BK][BSTR] = (bf16(*)[BK][BSTR])(smem + NSTG * A_STG);

    int tm, tn;
    if (TRI) {
        int x = blockIdx.x;
        int r = (int)((-1.f + sqrtf(1.f + 8.f * (float)x)) * 0.5f);
        while ((r + 1) * (r + 2) / 2 <= x) ++r;
        while (r * (r + 1) / 2 > x) --r;
        tm = r; tn = x - r * (r + 1) / 2;
    } else { tn = blockIdx.x; tm = blockIdx.y; }

    const int m0 = tm * BM;
    const int n0 = tn * BN;
    A += (long)blockIdx.z * sA;
    B += (long)blockIdx.z * sB;

    int Keff = K;
    if (KLIM) { int lim = 3 * (m0 + BM); Keff = (lim < K) ? lim : K; }

    const int tid  = threadIdx.x;
    const int lane = tid & 31;
    const int warp = tid >> 5;
    const int wm   = warp >> 1;
    const int wn   = warp & 1;

    float acc[2][8][4];
#pragma unroll
    for (int a = 0; a < 2; a++)
#pragma unroll
        for (int b = 0; b < 8; b++)
#pragma unroll
            for (int c = 0; c < 4; c++) acc[a][b][c] = 0.f;

    const int ktiles = Keff / BK;

    auto load_tiles = [&](int buf, int kt) {
#pragma unroll
        for (int i = 0; i < 4; i++) {
            int seg = tid + 256 * i;
            int r = seg >> 3, c = (seg & 7) * 8;
            uint32_t dst = (uint32_t)__cvta_generic_to_shared(&As[buf][r][c]);
            cp_async16(dst, A + (long)(m0 + r) * lda + kt + c, true);
        }
#pragma unroll
        for (int i = 0; i < 4; i++) {
            int seg = tid + 256 * i;
            int r = seg >> 4, c = (seg & 15) * 8;
            uint32_t dst = (uint32_t)__cvta_generic_to_shared(&Bs[buf][r][c]);
            bool ok = (n0 + c) < N;
            const bf16* src = ok ? (B + (long)(kt + r) * ldb + n0 + c) : B;
            cp_async16(dst, src, ok);
        }
        cp_commit();
    };

    load_tiles(0, 0);
    if (ktiles > 1) load_tiles(1, BK);

    for (int t = 0; t < ktiles; t++) {
        const int buf = t % NSTG;
        if (t + 2 < ktiles) {
            load_tiles((t + 2) % NSTG, (t + 2) * BK);
            asm volatile("cp.async.wait_group 2;" ::: "memory");
        } else if (t + 1 < ktiles) {
            asm volatile("cp.async.wait_group 1;" ::: "memory");
        } else {
            asm volatile("cp.async.wait_group 0;" ::: "memory");
        }
        __syncthreads();

#pragma unroll
        for (int kk = 0; kk < 4; kk++) {
            uint32_t af[2][4];
#pragma unroll
            for (int mt = 0; mt < 2; mt++) {
                uint32_t addr = (uint32_t)__cvta_generic_to_shared(
                    &As[buf][wm * 32 + mt * 16 + (lane & 15)][kk * 16 + (lane >> 4) * 8]);
                ldsm_x4(af[mt], addr);
            }
            uint32_t bfr[4][4];
#pragma unroll
            for (int np = 0; np < 4; np++) {
                uint32_t addr = (uint32_t)__cvta_generic_to_shared(
                    &Bs[buf][kk * 16 + (lane & 15)][wn * 64 + np * 16 + (lane >> 4) * 8]);
                ldsm_x4_t(bfr[np], addr);
            }
#pragma unroll
            for (int mt = 0; mt < 2; mt++)
#pragma unroll
                for (int nt = 0; nt < 8; nt++)
                    mma_bf16(acc[mt][nt], af[mt], &bfr[nt >> 1][(nt & 1) * 2]);
        }
        __syncthreads();
    }

    // ---- epilogue ----
    const int r  = lane >> 2;
    const int c2 = (lane & 3) * 2;

    auto emit = [&](int m, int n, float v0, float v1) {
        v0 *= alpha; v1 *= alpha;
        if (EPI == 0) {
            float* C = (float*)Cv + (long)blockIdx.z * sC;
            C[(long)m * ldc + n]     = v0;
            C[(long)m * ldc + n + 1] = v1;
        } else if (EPI == 1) {
            bf16* C = (bf16*)Cv + (long)blockIdx.z * sC;
            bf16 h0, l0, h1, l1;
            split_bf16(v0, h0, l0); split_bf16(v1, h1, l1);
            __nv_bfloat162 hi2 = __nv_bfloat162(h0, h1);
            __nv_bfloat162 lo2 = __nv_bfloat162(l0, l1);
            long base = (long)m * ldc + n;
            *(__nv_bfloat162*)&C[base] = hi2;
            *(__nv_bfloat162*)&C[base + off2] = hi2;
            *(__nv_bfloat162*)&C[base + 2 * off2] = lo2;
        } else {
            bf16* C = (bf16*)Cv + (long)blockIdx.z * sC;
            bf16 h0, l0, h1, l1;
            split_bf16(v0, h0, l0); split_bf16(v1, h1, l1);
            __nv_bfloat162 hi2 = __nv_bfloat162(h0, h1);
            __nv_bfloat162 lo2 = __nv_bfloat162(l0, l1);
            *(__nv_bfloat162*)&C[(long)(3 * m)     * ldc + n] = hi2;
            *(__nv_bfloat162*)&C[(long)(3 * m + 1) * ldc + n] = lo2;
            *(__nv_bfloat162*)&C[(long)(3 * m + 2) * ldc + n] = hi2;
        }
    };

#pragma unroll
    for (int mt = 0; mt < 2; mt++) {
#pragma unroll
        for (int nt = 0; nt < 8; nt++) {
            int m = m0 + wm * 32 + mt * 16 + r;
            int n = n0 + wn * 64 + nt * 8 + c2;
            if (n < N) {
                emit(m,     n, acc[mt][nt][0], acc[mt][nt][1]);
                emit(m + 8, n, acc[mt][nt][2], acc[mt][nt][3]);
            }
        }
    }
}

// ---------------- vectorized converters ----------------
union BV4 { bf16 b[4]; uint2 u; };

__global__ void convA4_k(const float* __restrict__ src, bf16* __restrict__ dst,
                         int M, int K, int lda, long ssrc)
{
    src += (long)blockIdx.z * ssrc;
    dst += (long)blockIdx.z * M * 3 * K;
    int K4 = K >> 2;
    long total = (long)M * K4;
    for (long idx = (long)blockIdx.x * blockDim.x + threadIdx.x; idx < total;
         idx += (long)gridDim.x * blockDim.x) {
        int m = (int)(idx / K4), k = (int)(idx % K4) * 4;
        float4 x = *(const float4*)(src + (long)m * lda + k);
        BV4 hv, lv;
        split_bf16(x.x, hv.b[0], lv.b[0]);
        split_bf16(x.y, hv.b[1], lv.b[1]);
        split_bf16(x.z, hv.b[2], lv.b[2]);
        split_bf16(x.w, hv.b[3], lv.b[3]);
        bf16* row = dst + (long)m * 3 * K;
        *(uint2*)&row[k]         = hv.u;
        *(uint2*)&row[K + k]     = hv.u;
        *(uint2*)&row[2 * K + k] = lv.u;
    }
}

__global__ void convB4_k(const float* __restrict__ src, bf16* __restrict__ dst,
                         int K, int N, int ldb, long ssrc)
{
    src += (long)blockIdx.z * ssrc;
    dst += (long)blockIdx.z * 3 * K * N;
    int N4 = N >> 2;
    long total = (long)K * N4;
    for (long idx = (long)blockIdx.x * blockDim.x + threadIdx.x; idx < total;
         idx += (long)gridDim.x * blockDim.x) {
        int k = (int)(idx / N4), n = (int)(idx % N4) * 4;
        float4 x = *(const float4*)(src + (long)k * ldb + n);
        BV4 hv, lv;
        split_bf16(x.x, hv.b[0], lv.b[0]);
        split_bf16(x.y, hv.b[1], lv.b[1]);
        split_bf16(x.z, hv.b[2], lv.b[2]);
        split_bf16(x.w, hv.b[3], lv.b[3]);
        *(uint2*)&dst[(long)k * N + n]           = hv.u;
        *(uint2*)&dst[((long)K + k) * N + n]     = lv.u;
        *(uint2*)&dst[((long)2 * K + k) * N + n] = hv.u;
    }
}

__global__ void convBt_k(const float* __restrict__ src, bf16* __restrict__ dst,
                         int K, int N, int lds)
{
    long total = (long)K * N;
    for (long idx = (long)blockIdx.x * blockDim.x + threadIdx.x; idx < total;
         idx += (long)gridDim.x * blockDim.x) {
        int k = (int)(idx / N), n = (int)(idx % N);
        float x = src[(long)n * lds + k];
        bf16 hi, lo; split_bf16(x, hi, lo);
        dst[(long)k * N + n] = hi;
        dst[((long)K + k) * N + n] = lo;
        dst[((long)2 * K + k) * N + n] = hi;
    }
}

// ---------------- elementwise kernels ----------------
__global__ void rmsnorm_rows_k(float* x, const float* __restrict__ w, int W)
{
    int row = blockIdx.x;
    float* p = x + (long)row * W;
    __shared__ float red[256];
    int tid = threadIdx.x;
    float ss = 0.f;
    for (int i = tid; i < W; i += 256) { float v = p[i]; ss += v * v; }
    red[tid] = ss; __syncthreads();
    for (int st = 128; st > 0; st >>= 1) {
        if (tid < st) red[tid] += red[tid + st];
        __syncthreads();
    }
    float r = rsqrtf(red[0] / (float)W + 1e-6f);
    for (int i = tid; i < W; i += 256) p[i] = p[i] * r * w[i];
}

__global__ void build_kfull_k(const float* __restrict__ kv, const float* __restrict__ lnw,
                              const float* __restrict__ cosb, const float* __restrict__ sinb,
                              float* __restrict__ kfull)
{
    int s = blockIdx.x;
    int tid = threadIdx.x;
    const float* row = kv + (long)s * LATENT;
    float* out = kfull + (long)s * LATENT;
    __shared__ float red[256];
    float ss = 0.f;
    for (int i = tid; i < KV_LORA; i += 256) { float v = row[i]; ss += v * v; }
    red[tid] = ss; __syncthreads();
    for (int st = 128; st > 0; st >>= 1) {
        if (tid < st) red[tid] += red[tid + st];
        __syncthreads();
    }
    float r = rsqrtf(red[0] / (float)KV_LORA + 1e-6f);
    for (int i = tid; i < KV_LORA; i += 256) out[i] = row[i] * r * lnw[i];
    if (tid < ROPE_D) {
        int j = tid;
        float x = row[KV_LORA + j];
        float rot = (j < 32) ? -row[KV_LORA + j + 32] : row[KV_LORA + j - 32];
        out[KV_LORA + j] = x * cosb[s * ROPE_D + j] + rot * sinb[s * ROPE_D + j];
    }
}

__global__ void rope_qpe2_k(const float* __restrict__ q,
                            const float* __restrict__ cosb, const float* __restrict__ sinb,
                            bf16* __restrict__ qfull2)
{
    int s = blockIdx.x;
    int h = blockIdx.y;
    int j = threadIdx.x;
    const float* x = q + (long)s * QBN + h * Q_HEAD + NOPE_D;
    float v = x[j];
    float rot = (j < 32) ? -x[j + 32] : x[j - 32];
    float val = v * cosb[s * ROPE_D + j] + rot * sinb[s * ROPE_D + j];
    bf16 hi, lo; split_bf16(val, hi, lo);
    bf16* row = qfull2 + ((long)h * S_LEN + s) * (3 * LATENT);
    row[KV_LORA + j] = hi;
    row[LATENT + KV_LORA + j] = hi;
    row[2 * LATENT + KV_LORA + j] = lo;
}

__global__ void softmax_probs2_k(const float* __restrict__ scores, bf16* __restrict__ probs2)
{
    int q = blockIdx.x;
    int h = blockIdx.y;
    int tid = threadIdx.x;
    const float* row = scores + ((long)h * S_LEN + q) * S_LEN;
    bf16* orow = probs2 + ((long)h * S_LEN + q) * (3 * S_LEN);
    int n = q + 1;
    int imax = ((q >> 7) + 1) << 7;
    __shared__ float red[256];

    int i0 = tid * 4;
    bool act = i0 < imax;
    float a[4] = {0.f, 0.f, 0.f, 0.f};
    if (act) { float4 v = *(const float4*)(row + i0); a[0]=v.x; a[1]=v.y; a[2]=v.z; a[3]=v.w; }

    float mx = -3.4e38f;
#pragma unroll
    for (int j = 0; j < 4; j++)
        if (i0 + j < n) mx = fmaxf(mx, a[j]);
    red[tid] = mx; __syncthreads();
    for (int st = 128; st > 0; st >>= 1) {
        if (tid < st) red[tid] = fmaxf(red[tid], red[tid + st]);
        __syncthreads();
    }
    mx = red[0];
    __syncthreads();

    float sum = 0.f;
#pragma unroll
    for (int j = 0; j < 4; j++) {
        a[j] = (i0 + j < n) ? __expf(a[j] - mx) : 0.f;
        sum += a[j];
    }
    red[tid] = sum; __syncthreads();
    for (int st = 128; st > 0; st >>= 1) {
        if (tid < st) red[tid] += red[tid + st];
        __syncthreads();
    }
    float inv = 1.f / red[0];

    if (act) {
        __align__(8) bf16 buf[12];
#pragma unroll
        for (int j = 0; j < 4; j++) {
            float p = a[j] * inv;
            bf16 hi, lo; split_bf16(p, hi, lo);
            buf[3 * j + 0] = hi;
            buf[3 * j + 1] = hi;
            buf[3 * j + 2] = lo;
        }
        uint2* dst = (uint2*)(orow + 3 * i0);
        const uint2* sb = (const uint2*)buf;
        dst[0] = sb[0]; dst[1] = sb[1]; dst[2] = sb[2];
    }
}

// ---------------- host-side launchers (stream-aware) ----------------
template<int EPI, int TRI, int KLIM>
static void gemm(cudaStream_t st, const bf16* A, const bf16* B, void* C,
                 int M, int N, int K, int lda, int ldb, int ldc,
                 long sA, long sB, long sC, int batch, float alpha, int off2)
{
    cudaFuncSetAttribute(gemm_t<EPI, TRI, KLIM>,
                         cudaFuncAttributeMaxDynamicSharedMemorySize, SMEM_BYTES);
    dim3 grid;
    if (TRI) {
        int t = M / BM;
        grid = dim3(t * (t + 1) / 2, 1, batch);
    } else {
        grid = dim3((N + BN - 1) / BN, M / BM, batch);
    }
    gemm_t<EPI, TRI, KLIM><<<grid, 256, SMEM_BYTES, st>>>(A, B, C, M, N, K, lda, ldb, ldc,
                                                          sA, sB, sC, alpha, off2);
}
static void convA(cudaStream_t st, const float* src, bf16* dst,
                  int M, int K, int lda, long ssrc, int batch)
{
    long total = (long)M * (K >> 2);
    int blocks = (int)((total + 255) / 256);
    if (blocks > 2048) blocks = 2048;
    convA4_k<<<dim3(blocks, 1, batch), 256, 0, st>>>(src, dst, M, K, lda, ssrc);
}
static void convB(cudaStream_t st, const float* src, bf16* dst,
                  int K, int N, int ldb, long ssrc, int batch)
{
    long total = (long)K * (N >> 2);
    int blocks = (int)((total + 255) / 256);
    if (blocks > 2048) blocks = 2048;
    convB4_k<<<dim3(blocks, 1, batch), 256, 0, st>>>(src, dst, K, N, ldb, ssrc);
}

extern "C" void kernel_launch(void* const* d_in, const int* in_sizes, int n_in,
                              void* d_out, int out_size)
{
    const float* h      = (const float*)d_in[0];
    const float* cosb   = (const float*)d_in[1];
    const float* sinb   = (const float*)d_in[2];
    const float* q_a_w  = (const float*)d_in[3];
    const float* q_a_ln = (const float*)d_in[4];
    const float* q_b_w  = (const float*)d_in[5];
    const float* kv_a_w = (const float*)d_in[6];
    const float* kv_ln  = (const float*)d_in[7];
    const float* kc_w   = (const float*)d_in[8];
    const float* vc_w   = (const float*)d_in[9];
    const float* o_w    = (const float*)d_in[10];
    float* out = (float*)d_out;

    bf16 *p_h2, *p_qaw2, *p_qa2, *p_qbw2, *p_qn2, *p_kc2, *p_kvaw2, *p_lat2, *p_kT2;
    bf16 *p_vc2, *p_qfull2, *p_veff2, *p_probs2, *p_bigo2, *p_ow2;
    float *p_qa, *p_q, *p_kv, *p_kfull, *p_scores;
    cudaGetSymbolAddress((void**)&p_h2,     g_h2);
    cudaGetSymbolAddress((void**)&p_qaw2,   g_qaw2);
    cudaGetSymbolAddress((void**)&p_qa2,    g_qa2);
    cudaGetSymbolAddress((void**)&p_qbw2,   g_qbw2);
    cudaGetSymbolAddress((void**)&p_qn2,    g_qn2);
    cudaGetSymbolAddress((void**)&p_kc2,    g_kc2);
    cudaGetSymbolAddress((void**)&p_kvaw2,  g_kvaw2);
    cudaGetSymbolAddress((void**)&p_lat2,   g_lat2);
    cudaGetSymbolAddress((void**)&p_kT2,    g_kT2);
    cudaGetSymbolAddress((void**)&p_vc2,    g_vc2);
    cudaGetSymbolAddress((void**)&p_qfull2, g_qfull2);
    cudaGetSymbolAddress((void**)&p_veff2,  g_veff2);
    cudaGetSymbolAddress((void**)&p_probs2, g_probs2);
    cudaGetSymbolAddress((void**)&p_bigo2,  g_bigo2);
    cudaGetSymbolAddress((void**)&p_ow2,    g_ow2);
    cudaGetSymbolAddress((void**)&p_qa,     g_qa);
    cudaGetSymbolAddress((void**)&p_q,      g_q);
    cudaGetSymbolAddress((void**)&p_kv,     g_kv);
    cudaGetSymbolAddress((void**)&p_kfull,  g_kfull);
    cudaGetSymbolAddress((void**)&p_scores, g_scores);

    double mscale = 0.1 * log(40.0) + 1.0;
    const float SCALE = (float)(pow((double)Q_HEAD, -0.5) * mscale * mscale);

    // main stream = legacy default (captured by harness); s2 = forked side stream
    cudaStream_t s0 = (cudaStream_t)0;
    cudaStream_t s2;
    cudaStreamCreateWithFlags(&s2, cudaStreamNonBlocking);
    cudaEvent_t e1, e2, e3;
    cudaEventCreateWithFlags(&e1, cudaEventDisableTiming);
    cudaEventCreateWithFlags(&e2, cudaEventDisableTiming);
    cudaEventCreateWithFlags(&e3, cudaEventDisableTiming);

    // ---- stream0: input conversion, then fork ----
    convA(s0, h, p_h2, S_LEN, D_MODEL, D_MODEL, 0, 1);
    cudaEventRecord(e1, s0);
    cudaStreamWaitEvent(s2, e1, 0);

    // ---- s2: weight converters + kv-path + veff (independent of q-path) ----
    convB(s2, q_b_w,  p_qbw2,  Q_LORA, QBN, QBN, 0, 1);
    convB(s2, kc_w,   p_kc2,   NOPE_D, KV_LORA, KV_LORA, (long)NOPE_D * KV_LORA, H_HEADS);
    cudaEventRecord(e3, s2);             // qbw2 + kc2 ready (needed by stream0 GEMM3/GEMM6)
    convB(s2, kv_a_w, p_kvaw2, D_MODEL, LATENT, LATENT, 0, 1);
    // kv = h @ kv_a_w
    gemm<0,0,0>(s2, p_h2, p_kvaw2, p_kv, S_LEN, LATENT, 3 * D_MODEL,
                3 * D_MODEL, LATENT, LATENT, 0, 0, 0, 1, 1.f, 0);
    build_kfull_k<<<S_LEN, 256, 0, s2>>>(p_kv, kv_ln, cosb, sinb, p_kfull);
    convA(s2, p_kfull, p_lat2, S_LEN, KV_LORA, LATENT, 0, 1);
    {
        long total = (long)LATENT * S_LEN;
        int blocks = (int)((total + 255) / 256);
        convBt_k<<<blocks, 256, 0, s2>>>(p_kfull, p_kT2, LATENT, S_LEN, LATENT);
    }
    convB(s2, vc_w, p_vc2, KV_LORA, VDIM, VDIM, (long)KV_LORA * VDIM, H_HEADS);
    // V_eff[h] = latent @ vc_w[h], fused splitB-interleave epilogue
    gemm<2,0,0>(s2, p_lat2, p_vc2, p_veff2,
                S_LEN, VDIM, 3 * KV_LORA,
                3 * KV_LORA, VDIM, VDIM,
                0, (long)3 * KV_LORA * VDIM, (long)3 * S_LEN * VDIM,
                H_HEADS, 1.f, 0);
    convB(s2, o_w, p_ow2, OUTW, D_MODEL, D_MODEL, 0, 1);
    cudaEventRecord(e2, s2);

    // ---- stream0: q-path ----
    convB(s0, q_a_w, p_qaw2, D_MODEL, Q_LORA, Q_LORA, 0, 1);
    gemm<0,0,0>(s0, p_h2, p_qaw2, p_qa, S_LEN, Q_LORA, 3 * D_MODEL,
                3 * D_MODEL, Q_LORA, Q_LORA, 0, 0, 0, 1, 1.f, 0);
    rmsnorm_rows_k<<<S_LEN, 256, 0, s0>>>(p_qa, q_a_ln, Q_LORA);
    convA(s0, p_qa, p_qa2, S_LEN, Q_LORA, Q_LORA, 0, 1);
    cudaStreamWaitEvent(s0, e3, 0);      // need qbw2 + kc2
    gemm<0,0,0>(s0, p_qa2, p_qbw2, p_q, S_LEN, QBN, 3 * Q_LORA,
                3 * Q_LORA, QBN, QBN, 0, 0, 0, 1, 1.f, 0);
    convA(s0, p_q, p_qn2, S_LEN, NOPE_D, QBN, (long)Q_HEAD, H_HEADS);
    gemm<1,0,0>(s0, p_qn2, p_kc2, p_qfull2,
                S_LEN, KV_LORA, 3 * NOPE_D,
                3 * NOPE_D, KV_LORA, 3 * LATENT,
                (long)S_LEN * 3 * NOPE_D, (long)3 * NOPE_D * KV_LORA,
                (long)S_LEN * 3 * LATENT, H_HEADS, 1.f, LATENT);
    {
        dim3 grid(S_LEN, H_HEADS);
        rope_qpe2_k<<<grid, 64, 0, s0>>>(p_q, cosb, sinb, p_qfull2);
    }

    // ---- join, then attention tail ----
    cudaStreamWaitEvent(s0, e2, 0);      // need kT2, veff2, ow2
    gemm<0,1,0>(s0, p_qfull2, p_kT2, p_scores,
                S_LEN, S_LEN, 3 * LATENT,
                3 * LATENT, S_LEN, S_LEN,
                (long)S_LEN * 3 * LATENT, 0, (long)S_LEN * S_LEN,
                H_HEADS, SCALE, 0);
    {
        dim3 grid(S_LEN, H_HEADS);
        softmax_probs2_k<<<grid, 256, 0, s0>>>(p_scores, p_probs2);
    }
    gemm<1,0,1>(s0, p_probs2, p_veff2, p_bigo2,
                S_LEN, VDIM, 3 * S_LEN,
                3 * S_LEN, VDIM, 3 * OUTW,
                (long)S_LEN * 3 * S_LEN, (long)3 * S_LEN * VDIM, (long)VDIM,
                H_HEADS, 1.f, OUTW);
    gemm<0,0,0>(s0, p_bigo2, p_ow2, out, S_LEN, D_MODEL, 3 * OUTW,
                3 * OUTW, D_MODEL, D_MODEL, 0, 0, 0, 1, 1.f, 0);
    // streams/events intentionally not destroyed: s2 may still be referenced by
    // an active capture; kernel_launch is invoked only a handful of times.
}

// round 14
// speedup vs baseline: 1.4916x; 1.0764x over previous
#include <cuda_runtime.h>
#include <cuda_bf16.h>
#include <math.h>
#include <stdint.h>

// ---------------- problem constants ----------------
#define S_LEN   1024
#define D_MODEL 5120
#define H_HEADS 128
#define Q_LORA  1536
#define KV_LORA 512
#define ROPE_D  64
#define NOPE_D  128
#define VDIM    128
#define Q_HEAD  192
#define LATENT  576
#define QBN     24576
#define OUTW    16384
#define HG      64            // head group size for pipelined attention tail

typedef __nv_bfloat16 bf16;

// ---------------- scratch (device globals; no allocation) ----------------
__device__ __align__(16) bf16 g_h2    [(size_t)S_LEN * 3 * D_MODEL];
__device__ __align__(16) bf16 g_qaw2  [(size_t)3 * D_MODEL * Q_LORA];
__device__ __align__(16) bf16 g_qa2   [(size_t)S_LEN * 3 * Q_LORA];
__device__ __align__(16) bf16 g_qbw2  [(size_t)3 * Q_LORA * QBN];
__device__ __align__(16) bf16 g_qn2   [(size_t)H_HEADS * S_LEN * 3 * NOPE_D];
__device__ __align__(16) bf16 g_kc2   [(size_t)H_HEADS * 3 * NOPE_D * KV_LORA];
__device__ __align__(16) bf16 g_kvaw2 [(size_t)3 * D_MODEL * LATENT];
__device__ __align__(16) bf16 g_lat2  [(size_t)S_LEN * 3 * KV_LORA];
__device__ __align__(16) bf16 g_kT2   [(size_t)3 * LATENT * S_LEN];
__device__ __align__(16) bf16 g_vc2   [(size_t)H_HEADS * 3 * KV_LORA * VDIM];
__device__ __align__(16) bf16 g_qfull2[(size_t)H_HEADS * S_LEN * 3 * LATENT];
__device__ __align__(16) bf16 g_veff2 [(size_t)H_HEADS * 3 * S_LEN * VDIM];
__device__ __align__(16) bf16 g_probs2[(size_t)H_HEADS * S_LEN * 3 * S_LEN];
__device__ __align__(16) bf16 g_bigo2 [(size_t)S_LEN * 3 * OUTW];
__device__ __align__(16) bf16 g_ow2   [(size_t)3 * OUTW * D_MODEL];
// fp32 intermediates
__device__ __align__(16) float g_qa   [(size_t)S_LEN * Q_LORA];
__device__ __align__(16) float g_q    [(size_t)S_LEN * QBN];      // reused as P2 scratch
__device__ __align__(16) float g_kv   [(size_t)S_LEN * LATENT];
__device__ __align__(16) float g_kfull[(size_t)S_LEN * LATENT];
__device__ __align__(16) float g_scores[(size_t)H_HEADS * S_LEN * S_LEN]; // head 0 region reused as P1

// ---------------- PTX helpers ----------------
__device__ __forceinline__ void cp_async16(uint32_t dst, const void* src, bool pred) {
    int sz = pred ? 16 : 0;
    asm volatile("cp.async.cg.shared.global [%0], [%1], 16, %2;\n"
                 :: "r"(dst), "l"(src), "r"(sz));
}
__device__ __forceinline__ void cp_commit() {
    asm volatile("cp.async.commit_group;\n" ::: "memory");
}
__device__ __forceinline__ void ldsm_x4(uint32_t* r, uint32_t addr) {
    asm volatile("ldmatrix.sync.aligned.m8n8.x4.shared.b16 {%0,%1,%2,%3}, [%4];\n"
                 : "=r"(r[0]), "=r"(r[1]), "=r"(r[2]), "=r"(r[3]) : "r"(addr));
}
__device__ __forceinline__ void ldsm_x4_t(uint32_t* r, uint32_t addr) {
    asm volatile("ldmatrix.sync.aligned.m8n8.x4.trans.shared.b16 {%0,%1,%2,%3}, [%4];\n"
                 : "=r"(r[0]), "=r"(r[1]), "=r"(r[2]), "=r"(r[3]) : "r"(addr));
}
__device__ __forceinline__ void mma_bf16(float* d, const uint32_t* a, const uint32_t* b) {
    asm volatile("mma.sync.aligned.m16n8k16.row.col.f32.bf16.bf16.f32 "
                 "{%0,%1,%2,%3},{%4,%5,%6,%7},{%8,%9},{%0,%1,%2,%3};\n"
                 : "+f"(d[0]), "+f"(d[1]), "+f"(d[2]), "+f"(d[3])
                 : "r"(a[0]), "r"(a[1]), "r"(a[2]), "r"(a[3]), "r"(b[0]), "r"(b[1]));
}

__device__ __forceinline__ void split_bf16(float x, bf16& hi, bf16& lo) {
    hi = __float2bfloat16(x);
    lo = __float2bfloat16(x - __bfloat162float(hi));
}

// ---------------- templated bf16 tensor-core GEMM: 128x128x64, 3-stage ----------------
#define BM 128
#define BN 128
#define BK 64
#define ASTR (BK + 8)
#define BSTR (BN + 8)
#define NSTG 3
#define A_STG (BM * ASTR)
#define B_STG (BK * BSTR)
#define SMEM_ELEMS (NSTG * (A_STG + B_STG))
#define SMEM_BYTES (SMEM_ELEMS * 2)

template<int EPI, int TRI, int KLIM>
__global__ void __launch_bounds__(256, 2) gemm_t(
    const bf16* __restrict__ A, const bf16* __restrict__ B, void* __restrict__ Cv,
    int M, int N, int K, int lda, int ldb, int ldc,
    long sA, long sB, long sC, float alpha, int off2)
{
    extern __shared__ bf16 smem[];
    bf16 (*As)[BM][ASTR] = (bf16(*)[BM][ASTR])smem;
    bf16 (*Bs)[BK][BSTR] = (bf16(*)[BK][BSTR])(smem + NSTG * A_STG);

    int tm, tn;
    if (TRI) {
        int x = blockIdx.x;
        int r = (int)((-1.f + sqrtf(1.f + 8.f * (float)x)) * 0.5f);
        while ((r + 1) * (r + 2) / 2 <= x) ++r;
        while (r * (r + 1) / 2 > x) --r;
        tm = r; tn = x - r * (r + 1) / 2;
    } else { tn = blockIdx.x; tm = blockIdx.y; }

    const int m0 = tm * BM;
    const int n0 = tn * BN;
    A += (long)blockIdx.z * sA;
    B += (long)blockIdx.z * sB;

    int Keff = K;
    if (KLIM) { int lim = 3 * (m0 + BM); Keff = (lim < K) ? lim : K; }

    const int tid  = threadIdx.x;
    const int lane = tid & 31;
    const int warp = tid >> 5;
    const int wm   = warp >> 1;
    const int wn   = warp & 1;

    float acc[2][8][4];
#pragma unroll
    for (int a = 0; a < 2; a++)
#pragma unroll
        for (int b = 0; b < 8; b++)
#pragma unroll
            for (int c = 0; c < 4; c++) acc[a][b][c] = 0.f;

    const int ktiles = Keff / BK;

    auto load_tiles = [&](int buf, int kt) {
#pragma unroll
        for (int i = 0; i < 4; i++) {
            int seg = tid + 256 * i;
            int r = seg >> 3, c = (seg & 7) * 8;
            uint32_t dst = (uint32_t)__cvta_generic_to_shared(&As[buf][r][c]);
            cp_async16(dst, A + (long)(m0 + r) * lda + kt + c, true);
        }
#pragma unroll
        for (int i = 0; i < 4; i++) {
            int seg = tid + 256 * i;
            int r = seg >> 4, c = (seg & 15) * 8;
            uint32_t dst = (uint32_t)__cvta_generic_to_shared(&Bs[buf][r][c]);
            bool ok = (n0 + c) < N;
            const bf16* src = ok ? (B + (long)(kt + r) * ldb + n0 + c) : B;
            cp_async16(dst, src, ok);
        }
        cp_commit();
    };

    load_tiles(0, 0);
    if (ktiles > 1) load_tiles(1, BK);

    for (int t = 0; t < ktiles; t++) {
        const int buf = t % NSTG;
        if (t + 2 < ktiles) {
            load_tiles((t + 2) % NSTG, (t + 2) * BK);
            asm volatile("cp.async.wait_group 2;" ::: "memory");
        } else if (t + 1 < ktiles) {
            asm volatile("cp.async.wait_group 1;" ::: "memory");
        } else {
            asm volatile("cp.async.wait_group 0;" ::: "memory");
        }
        __syncthreads();

#pragma unroll
        for (int kk = 0; kk < 4; kk++) {
            uint32_t af[2][4];
#pragma unroll
            for (int mt = 0; mt < 2; mt++) {
                uint32_t addr = (uint32_t)__cvta_generic_to_shared(
                    &As[buf][wm * 32 + mt * 16 + (lane & 15)][kk * 16 + (lane >> 4) * 8]);
                ldsm_x4(af[mt], addr);
            }
            uint32_t bfr[4][4];
#pragma unroll
            for (int np = 0; np < 4; np++) {
                uint32_t addr = (uint32_t)__cvta_generic_to_shared(
                    &Bs[buf][kk * 16 + (lane & 15)][wn * 64 + np * 16 + (lane >> 4) * 8]);
                ldsm_x4_t(bfr[np], addr);
            }
#pragma unroll
            for (int mt = 0; mt < 2; mt++)
#pragma unroll
                for (int nt = 0; nt < 8; nt++)
                    mma_bf16(acc[mt][nt], af[mt], &bfr[nt >> 1][(nt & 1) * 2]);
        }
        __syncthreads();
    }

    // ---- epilogue ----
    const int r  = lane >> 2;
    const int c2 = (lane & 3) * 2;

    auto emit = [&](int m, int n, float v0, float v1) {
        v0 *= alpha; v1 *= alpha;
        if (EPI == 0) {
            float* C = (float*)Cv + (long)blockIdx.z * sC;
            C[(long)m * ldc + n]     = v0;
            C[(long)m * ldc + n + 1] = v1;
        } else if (EPI == 1) {
            bf16* C = (bf16*)Cv + (long)blockIdx.z * sC;
            bf16 h0, l0, h1, l1;
            split_bf16(v0, h0, l0); split_bf16(v1, h1, l1);
            __nv_bfloat162 hi2 = __nv_bfloat162(h0, h1);
            __nv_bfloat162 lo2 = __nv_bfloat162(l0, l1);
            long base = (long)m * ldc + n;
            *(__nv_bfloat162*)&C[base] = hi2;
            *(__nv_bfloat162*)&C[base + off2] = hi2;
            *(__nv_bfloat162*)&C[base + 2 * off2] = lo2;
        } else {
            bf16* C = (bf16*)Cv + (long)blockIdx.z * sC;
            bf16 h0, l0, h1, l1;
            split_bf16(v0, h0, l0); split_bf16(v1, h1, l1);
            __nv_bfloat162 hi2 = __nv_bfloat162(h0, h1);
            __nv_bfloat162 lo2 = __nv_bfloat162(l0, l1);
            *(__nv_bfloat162*)&C[(long)(3 * m)     * ldc + n] = hi2;
            *(__nv_bfloat162*)&C[(long)(3 * m + 1) * ldc + n] = lo2;
            *(__nv_bfloat162*)&C[(long)(3 * m + 2) * ldc + n] = hi2;
        }
    };

#pragma unroll
    for (int mt = 0; mt < 2; mt++) {
#pragma unroll
        for (int nt = 0; nt < 8; nt++) {
            int m = m0 + wm * 32 + mt * 16 + r;
            int n = n0 + wn * 64 + nt * 8 + c2;
            if (n < N) {
                emit(m,     n, acc[mt][nt][0], acc[mt][nt][1]);
                emit(m + 8, n, acc[mt][nt][2], acc[mt][nt][3]);
            }
        }
    }
}

// ---------------- vectorized converters ----------------
union BV4 { bf16 b[4]; uint2 u; };

__global__ void convA4_k(const float* __restrict__ src, bf16* __restrict__ dst,
                         int M, int K, int lda, long ssrc)
{
    src += (long)blockIdx.z * ssrc;
    dst += (long)blockIdx.z * M * 3 * K;
    int K4 = K >> 2;
    long total = (long)M * K4;
    for (long idx = (long)blockIdx.x * blockDim.x + threadIdx.x; idx < total;
         idx += (long)gridDim.x * blockDim.x) {
        int m = (int)(idx / K4), k = (int)(idx % K4) * 4;
        float4 x = *(const float4*)(src + (long)m * lda + k);
        BV4 hv, lv;
        split_bf16(x.x, hv.b[0], lv.b[0]);
        split_bf16(x.y, hv.b[1], lv.b[1]);
        split_bf16(x.z, hv.b[2], lv.b[2]);
        split_bf16(x.w, hv.b[3], lv.b[3]);
        bf16* row = dst + (long)m * 3 * K;
        *(uint2*)&row[k]         = hv.u;
        *(uint2*)&row[K + k]     = hv.u;
        *(uint2*)&row[2 * K + k] = lv.u;
    }
}

__global__ void convB4_k(const float* __restrict__ src, bf16* __restrict__ dst,
                         int K, int N, int ldb, long ssrc)
{
    src += (long)blockIdx.z * ssrc;
    dst += (long)blockIdx.z * 3 * K * N;
    int N4 = N >> 2;
    long total = (long)K * N4;
    for (long idx = (long)blockIdx.x * blockDim.x + threadIdx.x; idx < total;
         idx += (long)gridDim.x * blockDim.x) {
        int k = (int)(idx / N4), n = (int)(idx % N4) * 4;
        float4 x = *(const float4*)(src + (long)k * ldb + n);
        BV4 hv, lv;
        split_bf16(x.x, hv.b[0], lv.b[0]);
        split_bf16(x.y, hv.b[1], lv.b[1]);
        split_bf16(x.z, hv.b[2], lv.b[2]);
        split_bf16(x.w, hv.b[3], lv.b[3]);
        *(uint2*)&dst[(long)k * N + n]           = hv.u;
        *(uint2*)&dst[((long)K + k) * N + n]     = lv.u;
        *(uint2*)&dst[((long)2 * K + k) * N + n] = hv.u;
    }
}

__global__ void convBt_k(const float* __restrict__ src, bf16* __restrict__ dst,
                         int K, int N, int lds)
{
    long total = (long)K * N;
    for (long idx = (long)blockIdx.x * blockDim.x + threadIdx.x; idx < total;
         idx += (long)gridDim.x * blockDim.x) {
        int k = (int)(idx / N), n = (int)(idx % N);
        float x = src[(long)n * lds + k];
        bf16 hi, lo; split_bf16(x, hi, lo);
        dst[(long)k * N + n] = hi;
        dst[((long)K + k) * N + n] = lo;
        dst[((long)2 * K + k) * N + n] = hi;
    }
}

// ---------------- elementwise kernels ----------------
__global__ void add2_k(const float* __restrict__ a, const float* __restrict__ b,
                       float* __restrict__ c, long n4)
{
    for (long i = (long)blockIdx.x * blockDim.x + threadIdx.x; i < n4;
         i += (long)gridDim.x * blockDim.x) {
        float4 x = ((const float4*)a)[i];
        float4 y = ((const float4*)b)[i];
        float4 z;
        z.x = x.x + y.x; z.y = x.y + y.y; z.z = x.z + y.z; z.w = x.w + y.w;
        ((float4*)c)[i] = z;
    }
}

__global__ void rmsnorm_rows_k(float* x, const float* __restrict__ w, int W)
{
    int row = blockIdx.x;
    float* p = x + (long)row * W;
    __shared__ float red[256];
    int tid = threadIdx.x;
    float ss = 0.f;
    for (int i = tid; i < W; i += 256) { float v = p[i]; ss += v * v; }
    red[tid] = ss; __syncthreads();
    for (int st = 128; st > 0; st >>= 1) {
        if (tid < st) red[tid] += red[tid + st];
        __syncthreads();
    }
    float r = rsqrtf(red[0] / (float)W + 1e-6f);
    for (int i = tid; i < W; i += 256) p[i] = p[i] * r * w[i];
}

__global__ void build_kfull_k(const float* __restrict__ kv, const float* __restrict__ lnw,
                              const float* __restrict__ cosb, const float* __restrict__ sinb,
                              float* __restrict__ kfull)
{
    int s = blockIdx.x;
    int tid = threadIdx.x;
    const float* row = kv + (long)s * LATENT;
    float* out = kfull + (long)s * LATENT;
    __shared__ float red[256];
    float ss = 0.f;
    for (int i = tid; i < KV_LORA; i += 256) { float v = row[i]; ss += v * v; }
    red[tid] = ss; __syncthreads();
    for (int st = 128; st > 0; st >>= 1) {
        if (tid < st) red[tid] += red[tid + st];
        __syncthreads();
    }
    float r = rsqrtf(red[0] / (float)KV_LORA + 1e-6f);
    for (int i = tid; i < KV_LORA; i += 256) out[i] = row[i] * r * lnw[i];
    if (tid < ROPE_D) {
        int j = tid;
        float x = row[KV_LORA + j];
        float rot = (j < 32) ? -row[KV_LORA + j + 32] : row[KV_LORA + j - 32];
        out[KV_LORA + j] = x * cosb[s * ROPE_D + j] + rot * sinb[s * ROPE_D + j];
    }
}

__global__ void rope_qpe2_k(const float* __restrict__ q,
                            const float* __restrict__ cosb, const float* __restrict__ sinb,
                            bf16* __restrict__ qfull2)
{
    int s = blockIdx.x;
    int h = blockIdx.y;
    int j = threadIdx.x;
    const float* x = q + (long)s * QBN + h * Q_HEAD + NOPE_D;
    float v = x[j];
    float rot = (j < 32) ? -x[j + 32] : x[j - 32];
    float val = v * cosb[s * ROPE_D + j] + rot * sinb[s * ROPE_D + j];
    bf16 hi, lo; split_bf16(val, hi, lo);
    bf16* row = qfull2 + ((long)h * S_LEN + s) * (3 * LATENT);
    row[KV_LORA + j] = hi;
    row[LATENT + KV_LORA + j] = hi;
    row[2 * LATENT + KV_LORA + j] = lo;
}

__global__ void softmax_probs2_k(const float* __restrict__ scores, bf16* __restrict__ probs2)
{
    int q = blockIdx.x;
    int h = blockIdx.y;
    int tid = threadIdx.x;
    const float* row = scores + ((long)h * S_LEN + q) * S_LEN;
    bf16* orow = probs2 + ((long)h * S_LEN + q) * (3 * S_LEN);
    int n = q + 1;
    int imax = ((q >> 7) + 1) << 7;
    __shared__ float red[256];

    int i0 = tid * 4;
    bool act = i0 < imax;
    float a[4] = {0.f, 0.f, 0.f, 0.f};
    if (act) { float4 v = *(const float4*)(row + i0); a[0]=v.x; a[1]=v.y; a[2]=v.z; a[3]=v.w; }

    float mx = -3.4e38f;
#pragma unroll
    for (int j = 0; j < 4; j++)
        if (i0 + j < n) mx = fmaxf(mx, a[j]);
    red[tid] = mx; __syncthreads();
    for (int st = 128; st > 0; st >>= 1) {
        if (tid < st) red[tid] = fmaxf(red[tid], red[tid + st]);
        __syncthreads();
    }
    mx = red[0];
    __syncthreads();

    float sum = 0.f;
#pragma unroll
    for (int j = 0; j < 4; j++) {
        a[j] = (i0 + j < n) ? __expf(a[j] - mx) : 0.f;
        sum += a[j];
    }
    red[tid] = sum; __syncthreads();
    for (int st = 128; st > 0; st >>= 1) {
        if (tid < st) red[tid] += red[tid + st];
        __syncthreads();
    }
    float inv = 1.f / red[0];

    if (act) {
        __align__(8) bf16 buf[12];
#pragma unroll
        for (int j = 0; j < 4; j++) {
            float p = a[j] * inv;
            bf16 hi, lo; split_bf16(p, hi, lo);
            buf[3 * j + 0] = hi;
            buf[3 * j + 1] = hi;
            buf[3 * j + 2] = lo;
        }
        uint2* dst = (uint2*)(orow + 3 * i0);
        const uint2* sb = (const uint2*)buf;
        dst[0] = sb[0]; dst[1] = sb[1]; dst[2] = sb[2];
    }
}

// ---------------- host-side launchers (stream-aware) ----------------
template<int EPI, int TRI, int KLIM>
static void gemm(cudaStream_t st, const bf16* A, const bf16* B, void* C,
                 int M, int N, int K, int lda, int ldb, int ldc,
                 long sA, long sB, long sC, int batch, float alpha, int off2)
{
    cudaFuncSetAttribute(gemm_t<EPI, TRI, KLIM>,
                         cudaFuncAttributeMaxDynamicSharedMemorySize, SMEM_BYTES);
    dim3 grid;
    if (TRI) {
        int t = M / BM;
        grid = dim3(t * (t + 1) / 2, 1, batch);
    } else {
        grid = dim3((N + BN - 1) / BN, M / BM, batch);
    }
    gemm_t<EPI, TRI, KLIM><<<grid, 256, SMEM_BYTES, st>>>(A, B, C, M, N, K, lda, ldb, ldc,
                                                          sA, sB, sC, alpha, off2);
}
static void convA(cudaStream_t st, const float* src, bf16* dst,
                  int M, int K, int lda, long ssrc, int batch)
{
    long total = (long)M * (K >> 2);
    int blocks = (int)((total + 255) / 256);
    if (blocks > 2048) blocks = 2048;
    convA4_k<<<dim3(blocks, 1, batch), 256, 0, st>>>(src, dst, M, K, lda, ssrc);
}
static void convB(cudaStream_t st, const float* src, bf16* dst,
                  int K, int N, int ldb, long ssrc, int batch)
{
    long total = (long)K * (N >> 2);
    int blocks = (int)((total + 255) / 256);
    if (blocks > 2048) blocks = 2048;
    convB4_k<<<dim3(blocks, 1, batch), 256, 0, st>>>(src, dst, K, N, ldb, ssrc);
}

extern "C" void kernel_launch(void* const* d_in, const int* in_sizes, int n_in,
                              void* d_out, int out_size)
{
    const float* h      = (const float*)d_in[0];
    const float* cosb   = (const float*)d_in[1];
    const float* sinb   = (const float*)d_in[2];
    const float* q_a_w  = (const float*)d_in[3];
    const float* q_a_ln = (const float*)d_in[4];
    const float* q_b_w  = (const float*)d_in[5];
    const float* kv_a_w = (const float*)d_in[6];
    const float* kv_ln  = (const float*)d_in[7];
    const float* kc_w   = (const float*)d_in[8];
    const float* vc_w   = (const float*)d_in[9];
    const float* o_w    = (const float*)d_in[10];
    float* out = (float*)d_out;

    bf16 *p_h2, *p_qaw2, *p_qa2, *p_qbw2, *p_qn2, *p_kc2, *p_kvaw2, *p_lat2, *p_kT2;
    bf16 *p_vc2, *p_qfull2, *p_veff2, *p_probs2, *p_bigo2, *p_ow2;
    float *p_qa, *p_q, *p_kv, *p_kfull, *p_scores;
    cudaGetSymbolAddress((void**)&p_h2,     g_h2);
    cudaGetSymbolAddress((void**)&p_qaw2,   g_qaw2);
    cudaGetSymbolAddress((void**)&p_qa2,    g_qa2);
    cudaGetSymbolAddress((void**)&p_qbw2,   g_qbw2);
    cudaGetSymbolAddress((void**)&p_qn2,    g_qn2);
    cudaGetSymbolAddress((void**)&p_kc2,    g_kc2);
    cudaGetSymbolAddress((void**)&p_kvaw2,  g_kvaw2);
    cudaGetSymbolAddress((void**)&p_lat2,   g_lat2);
    cudaGetSymbolAddress((void**)&p_kT2,    g_kT2);
    cudaGetSymbolAddress((void**)&p_vc2,    g_vc2);
    cudaGetSymbolAddress((void**)&p_qfull2, g_qfull2);
    cudaGetSymbolAddress((void**)&p_veff2,  g_veff2);
    cudaGetSymbolAddress((void**)&p_probs2, g_probs2);
    cudaGetSymbolAddress((void**)&p_bigo2,  g_bigo2);
    cudaGetSymbolAddress((void**)&p_ow2,    g_ow2);
    cudaGetSymbolAddress((void**)&p_qa,     g_qa);
    cudaGetSymbolAddress((void**)&p_q,      g_q);
    cudaGetSymbolAddress((void**)&p_kv,     g_kv);
    cudaGetSymbolAddress((void**)&p_kfull,  g_kfull);
    cudaGetSymbolAddress((void**)&p_scores, g_scores);

    double mscale = 0.1 * log(40.0) + 1.0;
    const float SCALE = (float)(pow((double)Q_HEAD, -0.5) * mscale * mscale);

    cudaStream_t s0 = (cudaStream_t)0;
    cudaStream_t s2;
    cudaStreamCreateWithFlags(&s2, cudaStreamNonBlocking);
    cudaEvent_t e1, e2, e3, e_sc0, e_pv0, e_pv1, e_P2;
    cudaEventCreateWithFlags(&e1,    cudaEventDisableTiming);
    cudaEventCreateWithFlags(&e2,    cudaEventDisableTiming);
    cudaEventCreateWithFlags(&e3,    cudaEventDisableTiming);
    cudaEventCreateWithFlags(&e_sc0, cudaEventDisableTiming);
    cudaEventCreateWithFlags(&e_pv0, cudaEventDisableTiming);
    cudaEventCreateWithFlags(&e_pv1, cudaEventDisableTiming);
    cudaEventCreateWithFlags(&e_P2,  cudaEventDisableTiming);

    // ---- stream0: input conversion, then fork ----
    convA(s0, h, p_h2, S_LEN, D_MODEL, D_MODEL, 0, 1);
    cudaEventRecord(e1, s0);
    cudaStreamWaitEvent(s2, e1, 0);

    // ---- s2: weight converters + kv-path + veff ----
    convB(s2, q_b_w,  p_qbw2,  Q_LORA, QBN, QBN, 0, 1);
    convB(s2, kc_w,   p_kc2,   NOPE_D, KV_LORA, KV_LORA, (long)NOPE_D * KV_LORA, H_HEADS);
    cudaEventRecord(e3, s2);
    convB(s2, kv_a_w, p_kvaw2, D_MODEL, LATENT, LATENT, 0, 1);
    gemm<0,0,0>(s2, p_h2, p_kvaw2, p_kv, S_LEN, LATENT, 3 * D_MODEL,
                3 * D_MODEL, LATENT, LATENT, 0, 0, 0, 1, 1.f, 0);
    build_kfull_k<<<S_LEN, 256, 0, s2>>>(p_kv, kv_ln, cosb, sinb, p_kfull);
    convA(s2, p_kfull, p_lat2, S_LEN, KV_LORA, LATENT, 0, 1);
    {
        long total = (long)LATENT * S_LEN;
        int blocks = (int)((total + 255) / 256);
        convBt_k<<<blocks, 256, 0, s2>>>(p_kfull, p_kT2, LATENT, S_LEN, LATENT);
    }
    convB(s2, vc_w, p_vc2, KV_LORA, VDIM, VDIM, (long)KV_LORA * VDIM, H_HEADS);
    gemm<2,0,0>(s2, p_lat2, p_vc2, p_veff2,
                S_LEN, VDIM, 3 * KV_LORA,
                3 * KV_LORA, VDIM, VDIM,
                0, (long)3 * KV_LORA * VDIM, (long)3 * S_LEN * VDIM,
                H_HEADS, 1.f, 0);
    convB(s2, o_w, p_ow2, OUTW, D_MODEL, D_MODEL, 0, 1);
    cudaEventRecord(e2, s2);

    // ---- stream0: q-path ----
    convB(s0, q_a_w, p_qaw2, D_MODEL, Q_LORA, Q_LORA, 0, 1);
    gemm<0,0,0>(s0, p_h2, p_qaw2, p_qa, S_LEN, Q_LORA, 3 * D_MODEL,
                3 * D_MODEL, Q_LORA, Q_LORA, 0, 0, 0, 1, 1.f, 0);
    rmsnorm_rows_k<<<S_LEN, 256, 0, s0>>>(p_qa, q_a_ln, Q_LORA);
    convA(s0, p_qa, p_qa2, S_LEN, Q_LORA, Q_LORA, 0, 1);
    cudaStreamWaitEvent(s0, e3, 0);
    gemm<0,0,0>(s0, p_qa2, p_qbw2, p_q, S_LEN, QBN, 3 * Q_LORA,
                3 * Q_LORA, QBN, QBN, 0, 0, 0, 1, 1.f, 0);
    convA(s0, p_q, p_qn2, S_LEN, NOPE_D, QBN, (long)Q_HEAD, H_HEADS);
    gemm<1,0,0>(s0, p_qn2, p_kc2, p_qfull2,
                S_LEN, KV_LORA, 3 * NOPE_D,
                3 * NOPE_D, KV_LORA, 3 * LATENT,
                (long)S_LEN * 3 * NOPE_D, (long)3 * NOPE_D * KV_LORA,
                (long)S_LEN * 3 * LATENT, H_HEADS, 1.f, LATENT);
    {
        dim3 grid(S_LEN, H_HEADS);
        rope_qpe2_k<<<grid, 64, 0, s0>>>(p_q, cosb, sinb, p_qfull2);
    }

    // ---- attention tail, pipelined over two head groups ----
    const long sQF = (long)S_LEN * 3 * LATENT;   // qfull2 per-head stride
    const long sSC = (long)S_LEN * S_LEN;        // scores per-head stride
    const long sPR = (long)S_LEN * 3 * S_LEN;    // probs2 per-head stride
    const long sVE = (long)3 * S_LEN * VDIM;     // veff2 per-head stride

    cudaStreamWaitEvent(s0, e2, 0);
    // scores group 0 (heads 0..63)
    gemm<0,1,0>(s0, p_qfull2, p_kT2, p_scores,
                S_LEN, S_LEN, 3 * LATENT,
                3 * LATENT, S_LEN, S_LEN,
                sQF, 0, sSC, HG, SCALE, 0);
    cudaEventRecord(e_sc0, s0);
    // scores group 1 (heads 64..127)
    gemm<0,1,0>(s0, p_qfull2 + HG * sQF, p_kT2, p_scores + HG * sSC,
                S_LEN, S_LEN, 3 * LATENT,
                3 * LATENT, S_LEN, S_LEN,
                sQF, 0, sSC, HG, SCALE, 0);

    // s2: softmax + PV for group 0 (overlaps scores group 1)
    cudaStreamWaitEvent(s2, e_sc0, 0);
    {
        dim3 grid(S_LEN, HG);
        softmax_probs2_k<<<grid, 256, 0, s2>>>(p_scores, p_probs2);
    }
    gemm<1,0,1>(s2, p_probs2, p_veff2, p_bigo2,
                S_LEN, VDIM, 3 * S_LEN,
                3 * S_LEN, VDIM, 3 * OUTW,
                sPR, sVE, (long)VDIM, HG, 1.f, OUTW);
    cudaEventRecord(e_pv0, s2);

    // s0: softmax + PV for group 1
    {
        dim3 grid(S_LEN, HG);
        softmax_probs2_k<<<grid, 256, 0, s0>>>(p_scores + HG * sSC, p_probs2 + HG * sPR);
    }
    gemm<1,0,1>(s0, p_probs2 + HG * sPR, p_veff2 + HG * sVE, p_bigo2 + (long)HG * VDIM,
                S_LEN, VDIM, 3 * S_LEN,
                3 * S_LEN, VDIM, 3 * OUTW,
                sPR, sVE, (long)VDIM, HG, 1.f, OUTW);
    cudaEventRecord(e_pv1, s0);

    // ---- out GEMM, split-K across both streams ----
    const int KH = (3 * OUTW) / 2;               // 24576
    float* P1 = p_scores;                        // reuse (dead after softmax; ordered via e_pv0)
    float* P2 = p_q;                             // reuse (dead after rope)
    // s0: P1 = bigo[:, :KH] @ ow[:KH, :]
    cudaStreamWaitEvent(s0, e_pv0, 0);
    gemm<0,0,0>(s0, p_bigo2, p_ow2, P1, S_LEN, D_MODEL, KH,
                3 * OUTW, D_MODEL, D_MODEL, 0, 0, 0, 1, 1.f, 0);
    // s2: P2 = bigo[:, KH:] @ ow[KH:, :]
    cudaStreamWaitEvent(s2, e_pv1, 0);
    gemm<0,0,0>(s2, p_bigo2 + KH, p_ow2 + (long)KH * D_MODEL, P2, S_LEN, D_MODEL, KH,
                3 * OUTW, D_MODEL, D_MODEL, 0, 0, 0, 1, 1.f, 0);
    cudaEventRecord(e_P2, s2);
    // s0: out = P1 + P2
    cudaStreamWaitEvent(s0, e_P2, 0);
    {
        long n4 = (long)S_LEN * D_MODEL / 4;
        int blocks = (int)((n4 + 255) / 256);
        if (blocks > 2048) blocks = 2048;
        add2_k<<<blocks, 256, 0, s0>>>(P1, P2, out, n4);
    }
    // streams/events intentionally not destroyed (may be referenced by active capture)
}

// round 15
// speedup vs baseline: 1.6175x; 1.0844x over previous
#include <cuda_runtime.h>
#include <cuda_bf16.h>
#include <math.h>
#include <stdint.h>

// ---------------- problem constants ----------------
#define S_LEN   1024
#define D_MODEL 5120
#define H_HEADS 128
#define Q_LORA  1536
#define KV_LORA 512
#define ROPE_D  64
#define NOPE_D  128
#define VDIM    128
#define Q_HEAD  192
#define LATENT  576
#define QBN     24576
#define OUTW    16384
#define HG      64            // head group size for pipelined attention tail
#define SKW     576           // scores split-K width (3 * (NOPE + ROPE))

typedef __nv_bfloat16 bf16;

// ---------------- scratch (device globals; no allocation) ----------------
__device__ __align__(16) bf16 g_h2    [(size_t)S_LEN * 3 * D_MODEL];
__device__ __align__(16) bf16 g_qaw2  [(size_t)3 * D_MODEL * Q_LORA];
__device__ __align__(16) bf16 g_qa2   [(size_t)S_LEN * 3 * Q_LORA];
__device__ __align__(16) bf16 g_qbw2  [(size_t)3 * Q_LORA * QBN];
__device__ __align__(16) bf16 g_kcA   [(size_t)H_HEADS * NOPE_D * 3 * KV_LORA]; // A-split kc_w per head
__device__ __align__(16) bf16 g_kvaw2 [(size_t)3 * D_MODEL * LATENT];
__device__ __align__(16) bf16 g_lat2  [(size_t)S_LEN * 3 * KV_LORA];
__device__ __align__(16) bf16 g_latT2 [(size_t)3 * KV_LORA * S_LEN];            // B-split latent^T
__device__ __align__(16) bf16 g_vc2   [(size_t)H_HEADS * 3 * KV_LORA * VDIM];
__device__ __align__(16) bf16 g_qsA   [(size_t)H_HEADS * S_LEN * SKW];          // scores A operand
__device__ __align__(16) bf16 g_ksB   [(size_t)H_HEADS * SKW * S_LEN];          // scores B operand
__device__ __align__(16) bf16 g_veff2 [(size_t)H_HEADS * 3 * S_LEN * VDIM];
__device__ __align__(16) bf16 g_probs2[(size_t)H_HEADS * S_LEN * 3 * S_LEN];
__device__ __align__(16) bf16 g_bigo2 [(size_t)S_LEN * 3 * OUTW];
__device__ __align__(16) bf16 g_ow2   [(size_t)3 * OUTW * D_MODEL];
// fp32 intermediates
__device__ __align__(16) float g_qa   [(size_t)S_LEN * Q_LORA];
__device__ __align__(16) float g_q    [(size_t)S_LEN * QBN];      // reused as P2 scratch
__device__ __align__(16) float g_kv   [(size_t)S_LEN * LATENT];
__device__ __align__(16) float g_kfull[(size_t)S_LEN * LATENT];
__device__ __align__(16) float g_scores[(size_t)H_HEADS * S_LEN * S_LEN]; // head-0 region reused as P1

// ---------------- PTX helpers ----------------
__device__ __forceinline__ void cp_async16(uint32_t dst, const void* src, bool pred) {
    int sz = pred ? 16 : 0;
    asm volatile("cp.async.cg.shared.global [%0], [%1], 16, %2;\n"
                 :: "r"(dst), "l"(src), "r"(sz));
}
__device__ __forceinline__ void cp_commit() {
    asm volatile("cp.async.commit_group;\n" ::: "memory");
}
__device__ __forceinline__ void ldsm_x4(uint32_t* r, uint32_t addr) {
    asm volatile("ldmatrix.sync.aligned.m8n8.x4.shared.b16 {%0,%1,%2,%3}, [%4];\n"
                 : "=r"(r[0]), "=r"(r[1]), "=r"(r[2]), "=r"(r[3]) : "r"(addr));
}
__device__ __forceinline__ void ldsm_x4_t(uint32_t* r, uint32_t addr) {
    asm volatile("ldmatrix.sync.aligned.m8n8.x4.trans.shared.b16 {%0,%1,%2,%3}, [%4];\n"
                 : "=r"(r[0]), "=r"(r[1]), "=r"(r[2]), "=r"(r[3]) : "r"(addr));
}
__device__ __forceinline__ void mma_bf16(float* d, const uint32_t* a, const uint32_t* b) {
    asm volatile("mma.sync.aligned.m16n8k16.row.col.f32.bf16.bf16.f32 "
                 "{%0,%1,%2,%3},{%4,%5,%6,%7},{%8,%9},{%0,%1,%2,%3};\n"
                 : "+f"(d[0]), "+f"(d[1]), "+f"(d[2]), "+f"(d[3])
                 : "r"(a[0]), "r"(a[1]), "r"(a[2]), "r"(a[3]), "r"(b[0]), "r"(b[1]));
}

__device__ __forceinline__ void split_bf16(float x, bf16& hi, bf16& lo) {
    hi = __float2bfloat16(x);
    lo = __float2bfloat16(x - __bfloat162float(hi));
}

// ---------------- templated bf16 tensor-core GEMM: 128x128x64, 3-stage ----------------
#define BM 128
#define BN 128
#define BK 64
#define ASTR (BK + 8)
#define BSTR (BN + 8)
#define NSTG 3
#define A_STG (BM * ASTR)
#define B_STG (BK * BSTR)
#define SMEM_ELEMS (NSTG * (A_STG + B_STG))
#define SMEM_BYTES (SMEM_ELEMS * 2)

template<int EPI, int TRI, int KLIM>
__global__ void __launch_bounds__(256, 2) gemm_t(
    const bf16* __restrict__ A, const bf16* __restrict__ B, void* __restrict__ Cv,
    int M, int N, int K, int lda, int ldb, int ldc,
    long sA, long sB, long sC, float alpha, int off2)
{
    extern __shared__ bf16 smem[];
    bf16 (*As)[BM][ASTR] = (bf16(*)[BM][ASTR])smem;
    bf16 (*Bs)[BK][BSTR] = (bf16(*)[BK][BSTR])(smem + NSTG * A_STG);

    int tm, tn;
    if (TRI) {
        int x = blockIdx.x;
        int r = (int)((-1.f + sqrtf(1.f + 8.f * (float)x)) * 0.5f);
        while ((r + 1) * (r + 2) / 2 <= x) ++r;
        while (r * (r + 1) / 2 > x) --r;
        tm = r; tn = x - r * (r + 1) / 2;
    } else { tn = blockIdx.x; tm = blockIdx.y; }

    const int m0 = tm * BM;
    const int n0 = tn * BN;
    A += (long)blockIdx.z * sA;
    B += (long)blockIdx.z * sB;

    int Keff = K;
    if (KLIM) { int lim = 3 * (m0 + BM); Keff = (lim < K) ? lim : K; }

    const int tid  = threadIdx.x;
    const int lane = tid & 31;
    const int warp = tid >> 5;
    const int wm   = warp >> 1;
    const int wn   = warp & 1;

    float acc[2][8][4];
#pragma unroll
    for (int a = 0; a < 2; a++)
#pragma unroll
        for (int b = 0; b < 8; b++)
#pragma unroll
            for (int c = 0; c < 4; c++) acc[a][b][c] = 0.f;

    const int ktiles = Keff / BK;

    auto load_tiles = [&](int buf, int kt) {
#pragma unroll
        for (int i = 0; i < 4; i++) {
            int seg = tid + 256 * i;
            int r = seg >> 3, c = (seg & 7) * 8;
            uint32_t dst = (uint32_t)__cvta_generic_to_shared(&As[buf][r][c]);
            bool okm = (m0 + r) < M;
            const bf16* src = okm ? (A + (long)(m0 + r) * lda + kt + c) : A;
            cp_async16(dst, src, okm);
        }
#pragma unroll
        for (int i = 0; i < 4; i++) {
            int seg = tid + 256 * i;
            int r = seg >> 4, c = (seg & 15) * 8;
            uint32_t dst = (uint32_t)__cvta_generic_to_shared(&Bs[buf][r][c]);
            bool ok = (n0 + c) < N;
            const bf16* src = ok ? (B + (long)(kt + r) * ldb + n0 + c) : B;
            cp_async16(dst, src, ok);
        }
        cp_commit();
    };

    load_tiles(0, 0);
    if (ktiles > 1) load_tiles(1, BK);

    for (int t = 0; t < ktiles; t++) {
        const int buf = t % NSTG;
        if (t + 2 < ktiles) {
            load_tiles((t + 2) % NSTG, (t + 2) * BK);
            asm volatile("cp.async.wait_group 2;" ::: "memory");
        } else if (t + 1 < ktiles) {
            asm volatile("cp.async.wait_group 1;" ::: "memory");
        } else {
            asm volatile("cp.async.wait_group 0;" ::: "memory");
        }
        __syncthreads();

#pragma unroll
        for (int kk = 0; kk < 4; kk++) {
            uint32_t af[2][4];
#pragma unroll
            for (int mt = 0; mt < 2; mt++) {
                uint32_t addr = (uint32_t)__cvta_generic_to_shared(
                    &As[buf][wm * 32 + mt * 16 + (lane & 15)][kk * 16 + (lane >> 4) * 8]);
                ldsm_x4(af[mt], addr);
            }
            uint32_t bfr[4][4];
#pragma unroll
            for (int np = 0; np < 4; np++) {
                uint32_t addr = (uint32_t)__cvta_generic_to_shared(
                    &Bs[buf][kk * 16 + (lane & 15)][wn * 64 + np * 16 + (lane >> 4) * 8]);
                ldsm_x4_t(bfr[np], addr);
            }
#pragma unroll
            for (int mt = 0; mt < 2; mt++)
#pragma unroll
                for (int nt = 0; nt < 8; nt++)
                    mma_bf16(acc[mt][nt], af[mt], &bfr[nt >> 1][(nt & 1) * 2]);
        }
        __syncthreads();
    }

    // ---- epilogue ----
    const int r  = lane >> 2;
    const int c2 = (lane & 3) * 2;

    auto emit = [&](int m, int n, float v0, float v1) {
        if (m >= M) return;
        v0 *= alpha; v1 *= alpha;
        if (EPI == 0) {
            float* C = (float*)Cv + (long)blockIdx.z * sC;
            C[(long)m * ldc + n]     = v0;
            C[(long)m * ldc + n + 1] = v1;
        } else if (EPI == 1) {
            bf16* C = (bf16*)Cv + (long)blockIdx.z * sC;
            bf16 h0, l0, h1, l1;
            split_bf16(v0, h0, l0); split_bf16(v1, h1, l1);
            __nv_bfloat162 hi2 = __nv_bfloat162(h0, h1);
            __nv_bfloat162 lo2 = __nv_bfloat162(l0, l1);
            long base = (long)m * ldc + n;
            *(__nv_bfloat162*)&C[base] = hi2;
            *(__nv_bfloat162*)&C[base + off2] = hi2;
            *(__nv_bfloat162*)&C[base + 2 * (long)off2] = lo2;
        } else {
            bf16* C = (bf16*)Cv + (long)blockIdx.z * sC;
            bf16 h0, l0, h1, l1;
            split_bf16(v0, h0, l0); split_bf16(v1, h1, l1);
            __nv_bfloat162 hi2 = __nv_bfloat162(h0, h1);
            __nv_bfloat162 lo2 = __nv_bfloat162(l0, l1);
            *(__nv_bfloat162*)&C[(long)(3 * m)     * ldc + n] = hi2;
            *(__nv_bfloat162*)&C[(long)(3 * m + 1) * ldc + n] = lo2;
            *(__nv_bfloat162*)&C[(long)(3 * m + 2) * ldc + n] = hi2;
        }
    };

#pragma unroll
    for (int mt = 0; mt < 2; mt++) {
#pragma unroll
        for (int nt = 0; nt < 8; nt++) {
            int m = m0 + wm * 32 + mt * 16 + r;
            int n = n0 + wn * 64 + nt * 8 + c2;
            if (n < N) {
                emit(m,     n, acc[mt][nt][0], acc[mt][nt][1]);
                emit(m + 8, n, acc[mt][nt][2], acc[mt][nt][3]);
            }
        }
    }
}

// ---------------- vectorized converters ----------------
union BV4 { bf16 b[4]; uint2 u; };

// A-style [hi|hi|lo], row stride 3K
__global__ void convA4_k(const float* __restrict__ src, bf16* __restrict__ dst,
                         int M, int K, int lda, long ssrc)
{
    src += (long)blockIdx.z * ssrc;
    dst += (long)blockIdx.z * M * 3 * K;
    int K4 = K >> 2;
    long total = (long)M * K4;
    for (long idx = (long)blockIdx.x * blockDim.x + threadIdx.x; idx < total;
         idx += (long)gridDim.x * blockDim.x) {
        int m = (int)(idx / K4), k = (int)(idx % K4) * 4;
        float4 x = *(const float4*)(src + (long)m * lda + k);
        BV4 hv, lv;
        split_bf16(x.x, hv.b[0], lv.b[0]);
        split_bf16(x.y, hv.b[1], lv.b[1]);
        split_bf16(x.z, hv.b[2], lv.b[2]);
        split_bf16(x.w, hv.b[3], lv.b[3]);
        bf16* row = dst + (long)m * 3 * K;
        *(uint2*)&row[k]         = hv.u;
        *(uint2*)&row[K + k]     = hv.u;
        *(uint2*)&row[2 * K + k] = lv.u;
    }
}

// A-style with custom offsets: hi at k and oh2+k, lo at olo+k; row stride rstride
__global__ void convAoff_k(const float* __restrict__ src, bf16* __restrict__ dst,
                           int M, int K, int lda, long ssrc, long sdst,
                           int rstride, int oh2, int olo)
{
    src += (long)blockIdx.z * ssrc;
    dst += (long)blockIdx.z * sdst;
    int K4 = K >> 2;
    long total = (long)M * K4;
    for (long idx = (long)blockIdx.x * blockDim.x + threadIdx.x; idx < total;
         idx += (long)gridDim.x * blockDim.x) {
        int m = (int)(idx / K4), k = (int)(idx % K4) * 4;
        float4 x = *(const float4*)(src + (long)m * lda + k);
        BV4 hv, lv;
        split_bf16(x.x, hv.b[0], lv.b[0]);
        split_bf16(x.y, hv.b[1], lv.b[1]);
        split_bf16(x.z, hv.b[2], lv.b[2]);
        split_bf16(x.w, hv.b[3], lv.b[3]);
        bf16* row = dst + (long)m * rstride;
        *(uint2*)&row[k]       = hv.u;
        *(uint2*)&row[oh2 + k] = hv.u;
        *(uint2*)&row[olo + k] = lv.u;
    }
}

// B-style [hi;lo;hi] rows
__global__ void convB4_k(const float* __restrict__ src, bf16* __restrict__ dst,
                         int K, int N, int ldb, long ssrc)
{
    src += (long)blockIdx.z * ssrc;
    dst += (long)blockIdx.z * 3 * K * N;
    int N4 = N >> 2;
    long total = (long)K * N4;
    for (long idx = (long)blockIdx.x * blockDim.x + threadIdx.x; idx < total;
         idx += (long)gridDim.x * blockDim.x) {
        int k = (int)(idx / N4), n = (int)(idx % N4) * 4;
        float4 x = *(const float4*)(src + (long)k * ldb + n);
        BV4 hv, lv;
        split_bf16(x.x, hv.b[0], lv.b[0]);
        split_bf16(x.y, hv.b[1], lv.b[1]);
        split_bf16(x.z, hv.b[2], lv.b[2]);
        split_bf16(x.w, hv.b[3], lv.b[3]);
        *(uint2*)&dst[(long)k * N + n]           = hv.u;
        *(uint2*)&dst[((long)K + k) * N + n]     = lv.u;
        *(uint2*)&dst[((long)2 * K + k) * N + n] = hv.u;
    }
}

// transposed B-style: dst[k][n] = src[n*lds+k], blocks [hi; lo; hi]
__global__ void convBt_k(const float* __restrict__ src, bf16* __restrict__ dst,
                         int K, int N, int lds)
{
    long total = (long)K * N;
    for (long idx = (long)blockIdx.x * blockDim.x + threadIdx.x; idx < total;
         idx += (long)gridDim.x * blockDim.x) {
        int k = (int)(idx / N), n = (int)(idx % N);
        float x = src[(long)n * lds + k];
        bf16 hi, lo; split_bf16(x, hi, lo);
        dst[(long)k * N + n] = hi;
        dst[((long)K + k) * N + n] = lo;
        dst[((long)2 * K + k) * N + n] = hi;
    }
}

// k_pe^T replicated into each head's ksB block: hi rows 128+k, 320+k; lo row 512+k
__global__ void convKpe_k(const float* __restrict__ kfull, bf16* __restrict__ ksB)
{
    int k = blockIdx.x;   // 0..63
    int h = blockIdx.y;   // 0..127
    bf16* base = ksB + (size_t)h * SKW * S_LEN;
    for (int n = threadIdx.x; n < S_LEN; n += blockDim.x) {
        float v = kfull[(long)n * LATENT + KV_LORA + k];
        bf16 hi, lo; split_bf16(v, hi, lo);
        base[(long)(128 + k) * S_LEN + n] = hi;
        base[(long)(320 + k) * S_LEN + n] = hi;
        base[(long)(512 + k) * S_LEN + n] = lo;
    }
}

// ---------------- elementwise kernels ----------------
__global__ void add2_k(const float* __restrict__ a, const float* __restrict__ b,
                       float* __restrict__ c, long n4)
{
    for (long i = (long)blockIdx.x * blockDim.x + threadIdx.x; i < n4;
         i += (long)gridDim.x * blockDim.x) {
        float4 x = ((const float4*)a)[i];
        float4 y = ((const float4*)b)[i];
        float4 z;
        z.x = x.x + y.x; z.y = x.y + y.y; z.z = x.z + y.z; z.w = x.w + y.w;
        ((float4*)c)[i] = z;
    }
}

__global__ void rmsnorm_rows_k(float* x, const float* __restrict__ w, int W)
{
    int row = blockIdx.x;
    float* p = x + (long)row * W;
    __shared__ float red[256];
    int tid = threadIdx.x;
    float ss = 0.f;
    for (int i = tid; i < W; i += 256) { float v = p[i]; ss += v * v; }
    red[tid] = ss; __syncthreads();
    for (int st = 128; st > 0; st >>= 1) {
        if (tid < st) red[tid] += red[tid + st];
        __syncthreads();
    }
    float r = rsqrtf(red[0] / (float)W + 1e-6f);
    for (int i = tid; i < W; i += 256) p[i] = p[i] * r * w[i];
}

__global__ void build_kfull_k(const float* __restrict__ kv, const float* __restrict__ lnw,
                              const float* __restrict__ cosb, const float* __restrict__ sinb,
                              float* __restrict__ kfull)
{
    int s = blockIdx.x;
    int tid = threadIdx.x;
    const float* row = kv + (long)s * LATENT;
    float* out = kfull + (long)s * LATENT;
    __shared__ float red[256];
    float ss = 0.f;
    for (int i = tid; i < KV_LORA; i += 256) { float v = row[i]; ss += v * v; }
    red[tid] = ss; __syncthreads();
    for (int st = 128; st > 0; st >>= 1) {
        if (tid < st) red[tid] += red[tid + st];
        __syncthreads();
    }
    float r = rsqrtf(red[0] / (float)KV_LORA + 1e-6f);
    for (int i = tid; i < KV_LORA; i += 256) out[i] = row[i] * r * lnw[i];
    if (tid < ROPE_D) {
        int j = tid;
        float x = row[KV_LORA + j];
        float rot = (j < 32) ? -row[KV_LORA + j + 32] : row[KV_LORA + j - 32];
        out[KV_LORA + j] = x * cosb[s * ROPE_D + j] + rot * sinb[s * ROPE_D + j];
    }
}

// rope(q_pe) -> qsA cols: hi at 128+j and 512+j, lo at 320+j
__global__ void rope_qpe3_k(const float* __restrict__ q,
                            const float* __restrict__ cosb, const float* __restrict__ sinb,
                            bf16* __restrict__ qsA)
{
    int s = blockIdx.x;
    int h = blockIdx.y;
    int j = threadIdx.x;
    const float* x = q + (long)s * QBN + h * Q_HEAD + NOPE_D;
    float v = x[j];
    float rot = (j < 32) ? -x[j + 32] : x[j - 32];
    float val = v * cosb[s * ROPE_D + j] + rot * sinb[s * ROPE_D + j];
    bf16 hi, lo; split_bf16(val, hi, lo);
    bf16* row = qsA + ((long)h * S_LEN + s) * SKW;
    row[128 + j] = hi;
    row[512 + j] = hi;
    row[320 + j] = lo;
}

__global__ void softmax_probs2_k(const float* __restrict__ scores, bf16* __restrict__ probs2)
{
    int q = blockIdx.x;
    int h = blockIdx.y;
    int tid = threadIdx.x;
    const float* row = scores + ((long)h * S_LEN + q) * S_LEN;
    bf16* orow = probs2 + ((long)h * S_LEN + q) * (3 * S_LEN);
    int n = q + 1;
    int imax = ((q >> 7) + 1) << 7;
    __shared__ float red[256];

    int i0 = tid * 4;
    bool act = i0 < imax;
    float a[4] = {0.f, 0.f, 0.f, 0.f};
    if (act) { float4 v = *(const float4*)(row + i0); a[0]=v.x; a[1]=v.y; a[2]=v.z; a[3]=v.w; }

    float mx = -3.4e38f;
#pragma unroll
    for (int j = 0; j < 4; j++)
        if (i0 + j < n) mx = fmaxf(mx, a[j]);
    red[tid] = mx; __syncthreads();
    for (int st = 128; st > 0; st >>= 1) {
        if (tid < st) red[tid] = fmaxf(red[tid], red[tid + st]);
        __syncthreads();
    }
    mx = red[0];
    __syncthreads();

    float sum = 0.f;
#pragma unroll
    for (int j = 0; j < 4; j++) {
        a[j] = (i0 + j < n) ? __expf(a[j] - mx) : 0.f;
        sum += a[j];
    }
    red[tid] = sum; __syncthreads();
    for (int st = 128; st > 0; st >>= 1) {
        if (tid < st) red[tid] += red[tid + st];
        __syncthreads();
    }
    float inv = 1.f / red[0];

    if (act) {
        __align__(8) bf16 buf[12];
#pragma unroll
        for (int j = 0; j < 4; j++) {
            float p = a[j] * inv;
            bf16 hi, lo; split_bf16(p, hi, lo);
            buf[3 * j + 0] = hi;
            buf[3 * j + 1] = hi;
            buf[3 * j + 2] = lo;
        }
        uint2* dst = (uint2*)(orow + 3 * i0);
        const uint2* sb = (const uint2*)buf;
        dst[0] = sb[0]; dst[1] = sb[1]; dst[2] = sb[2];
    }
}

// ---------------- host-side launchers (stream-aware) ----------------
template<int EPI, int TRI, int KLIM>
static void gemm(cudaStream_t st, const bf16* A, const bf16* B, void* C,
                 int M, int N, int K, int lda, int ldb, int ldc,
                 long sA, long sB, long sC, int batch, float alpha, int off2)
{
    cudaFuncSetAttribute(gemm_t<EPI, TRI, KLIM>,
                         cudaFuncAttributeMaxDynamicSharedMemorySize, SMEM_BYTES);
    dim3 grid;
    if (TRI) {
        int t = M / BM;
        grid = dim3(t * (t + 1) / 2, 1, batch);
    } else {
        grid = dim3((N + BN - 1) / BN, (M + BM - 1) / BM, batch);
    }
    gemm_t<EPI, TRI, KLIM><<<grid, 256, SMEM_BYTES, st>>>(A, B, C, M, N, K, lda, ldb, ldc,
                                                          sA, sB, sC, alpha, off2);
}
static void convA(cudaStream_t st, const float* src, bf16* dst,
                  int M, int K, int lda, long ssrc, int batch)
{
    long total = (long)M * (K >> 2);
    int blocks = (int)((total + 255) / 256);
    if (blocks > 2048) blocks = 2048;
    convA4_k<<<dim3(blocks, 1, batch), 256, 0, st>>>(src, dst, M, K, lda, ssrc);
}
static void convB(cudaStream_t st, const float* src, bf16* dst,
                  int K, int N, int ldb, long ssrc, int batch)
{
    long total = (long)K * (N >> 2);
    int blocks = (int)((total + 255) / 256);
    if (blocks > 2048) blocks = 2048;
    convB4_k<<<dim3(blocks, 1, batch), 256, 0, st>>>(src, dst, K, N, ldb, ssrc);
}

extern "C" void kernel_launch(void* const* d_in, const int* in_sizes, int n_in,
                              void* d_out, int out_size)
{
    const float* h      = (const float*)d_in[0];
    const float* cosb   = (const float*)d_in[1];
    const float* sinb   = (const float*)d_in[2];
    const float* q_a_w  = (const float*)d_in[3];
    const float* q_a_ln = (const float*)d_in[4];
    const float* q_b_w  = (const float*)d_in[5];
    const float* kv_a_w = (const float*)d_in[6];
    const float* kv_ln  = (const float*)d_in[7];
    const float* kc_w   = (const float*)d_in[8];
    const float* vc_w   = (const float*)d_in[9];
    const float* o_w    = (const float*)d_in[10];
    float* out = (float*)d_out;

    bf16 *p_h2, *p_qaw2, *p_qa2, *p_qbw2, *p_kcA, *p_kvaw2, *p_lat2, *p_latT2;
    bf16 *p_vc2, *p_qsA, *p_ksB, *p_veff2, *p_probs2, *p_bigo2, *p_ow2;
    float *p_qa, *p_q, *p_kv, *p_kfull, *p_scores;
    cudaGetSymbolAddress((void**)&p_h2,     g_h2);
    cudaGetSymbolAddress((void**)&p_qaw2,   g_qaw2);
    cudaGetSymbolAddress((void**)&p_qa2,    g_qa2);
    cudaGetSymbolAddress((void**)&p_qbw2,   g_qbw2);
    cudaGetSymbolAddress((void**)&p_kcA,    g_kcA);
    cudaGetSymbolAddress((void**)&p_kvaw2,  g_kvaw2);
    cudaGetSymbolAddress((void**)&p_lat2,   g_lat2);
    cudaGetSymbolAddress((void**)&p_latT2,  g_latT2);
    cudaGetSymbolAddress((void**)&p_vc2,    g_vc2);
    cudaGetSymbolAddress((void**)&p_qsA,    g_qsA);
    cudaGetSymbolAddress((void**)&p_ksB,    g_ksB);
    cudaGetSymbolAddress((void**)&p_veff2,  g_veff2);
    cudaGetSymbolAddress((void**)&p_probs2, g_probs2);
    cudaGetSymbolAddress((void**)&p_bigo2,  g_bigo2);
    cudaGetSymbolAddress((void**)&p_ow2,    g_ow2);
    cudaGetSymbolAddress((void**)&p_qa,     g_qa);
    cudaGetSymbolAddress((void**)&p_q,      g_q);
    cudaGetSymbolAddress((void**)&p_kv,     g_kv);
    cudaGetSymbolAddress((void**)&p_kfull,  g_kfull);
    cudaGetSymbolAddress((void**)&p_scores, g_scores);

    double mscale = 0.1 * log(40.0) + 1.0;
    const float SCALE = (float)(pow((double)Q_HEAD, -0.5) * mscale * mscale);

    cudaStream_t s0 = (cudaStream_t)0;
    cudaStream_t s2;
    cudaStreamCreateWithFlags(&s2, cudaStreamNonBlocking);
    cudaEvent_t e1, e2, e3, e_kl, e_sc0, e_pv0, e_pv1, e_P2;
    cudaEventCreateWithFlags(&e1,    cudaEventDisableTiming);
    cudaEventCreateWithFlags(&e2,    cudaEventDisableTiming);
    cudaEventCreateWithFlags(&e3,    cudaEventDisableTiming);
    cudaEventCreateWithFlags(&e_kl,  cudaEventDisableTiming);
    cudaEventCreateWithFlags(&e_sc0, cudaEventDisableTiming);
    cudaEventCreateWithFlags(&e_pv0, cudaEventDisableTiming);
    cudaEventCreateWithFlags(&e_pv1, cudaEventDisableTiming);
    cudaEventCreateWithFlags(&e_P2,  cudaEventDisableTiming);

    // ---- stream0: input conversion, then fork ----
    convA(s0, h, p_h2, S_LEN, D_MODEL, D_MODEL, 0, 1);
    cudaEventRecord(e1, s0);
    cudaStreamWaitEvent(s2, e1, 0);

    // ---- s2: weight converters + kv-path + KL + veff ----
    convB(s2, q_b_w, p_qbw2, Q_LORA, QBN, QBN, 0, 1);
    cudaEventRecord(e3, s2);                 // qbw2 ready for s0's q GEMM
    convA(s2, kc_w, p_kcA, NOPE_D, KV_LORA, KV_LORA, (long)NOPE_D * KV_LORA, H_HEADS);
    convB(s2, kv_a_w, p_kvaw2, D_MODEL, LATENT, LATENT, 0, 1);
    gemm<0,0,0>(s2, p_h2, p_kvaw2, p_kv, S_LEN, LATENT, 3 * D_MODEL,
                3 * D_MODEL, LATENT, LATENT, 0, 0, 0, 1, 1.f, 0);
    build_kfull_k<<<S_LEN, 256, 0, s2>>>(p_kv, kv_ln, cosb, sinb, p_kfull);
    {   // latent^T B-split (K=512, reads kfull transposed)
        long total = (long)3 * KV_LORA * S_LEN / 3;  // K*N
        int blocks = (int)(((long)KV_LORA * S_LEN + 255) / 256);
        if (blocks > 2048) blocks = 2048;
        convBt_k<<<blocks, 256, 0, s2>>>(p_kfull, p_latT2, KV_LORA, S_LEN, LATENT);
        (void)total;
    }
    {   // k_pe^T replicated into every head's ksB block
        dim3 grid(ROPE_D, H_HEADS);
        convKpe_k<<<grid, 256, 0, s2>>>(p_kfull, p_ksB);
    }
    // KL_h = kc_w[h] @ latent^T  -> ksB rows [0..127](hi), [192..319](hi), [384..511](lo)
    gemm<1,0,0>(s2, p_kcA, p_latT2, p_ksB,
                NOPE_D, S_LEN, 3 * KV_LORA,
                3 * KV_LORA, S_LEN, S_LEN,
                (long)NOPE_D * 3 * KV_LORA, 0, (long)SKW * S_LEN,
                H_HEADS, 1.f, 192 * S_LEN);
    cudaEventRecord(e_kl, s2);
    convA(s2, p_kfull, p_lat2, S_LEN, KV_LORA, LATENT, 0, 1);
    convB(s2, vc_w, p_vc2, KV_LORA, VDIM, VDIM, (long)KV_LORA * VDIM, H_HEADS);
    gemm<2,0,0>(s2, p_lat2, p_vc2, p_veff2,
                S_LEN, VDIM, 3 * KV_LORA,
                3 * KV_LORA, VDIM, VDIM,
                0, (long)3 * KV_LORA * VDIM, (long)3 * S_LEN * VDIM,
                H_HEADS, 1.f, 0);
    convB(s2, o_w, p_ow2, OUTW, D_MODEL, D_MODEL, 0, 1);
    cudaEventRecord(e2, s2);

    // ---- stream0: q-path ----
    convB(s0, q_a_w, p_qaw2, D_MODEL, Q_LORA, Q_LORA, 0, 1);
    gemm<0,0,0>(s0, p_h2, p_qaw2, p_qa, S_LEN, Q_LORA, 3 * D_MODEL,
                3 * D_MODEL, Q_LORA, Q_LORA, 0, 0, 0, 1, 1.f, 0);
    rmsnorm_rows_k<<<S_LEN, 256, 0, s0>>>(p_qa, q_a_ln, Q_LORA);
    convA(s0, p_qa, p_qa2, S_LEN, Q_LORA, Q_LORA, 0, 1);
    cudaStreamWaitEvent(s0, e3, 0);
    gemm<0,0,0>(s0, p_qa2, p_qbw2, p_q, S_LEN, QBN, 3 * Q_LORA,
                3 * Q_LORA, QBN, QBN, 0, 0, 0, 1, 1.f, 0);
    // q_nope -> qsA cols [0..127](hi), [384..511](hi), [192..319](lo)
    {
        long total = (long)S_LEN * (NOPE_D >> 2);
        int blocks = (int)((total + 255) / 256);
        if (blocks > 2048) blocks = 2048;
        convAoff_k<<<dim3(blocks, 1, H_HEADS), 256, 0, s0>>>(
            p_q, p_qsA, S_LEN, NOPE_D, QBN, (long)Q_HEAD, (long)S_LEN * SKW,
            SKW, 384, 192);
    }
    {
        dim3 grid(S_LEN, H_HEADS);
        rope_qpe3_k<<<grid, 64, 0, s0>>>(p_q, cosb, sinb, p_qsA);
    }

    // ---- attention tail, pipelined over two head groups ----
    const long sQS = (long)S_LEN * SKW;          // qsA per-head stride
    const long sKS = (long)SKW * S_LEN;          // ksB per-head stride
    const long sSC = (long)S_LEN * S_LEN;        // scores per-head stride
    const long sPR = (long)S_LEN * 3 * S_LEN;    // probs2 per-head stride
    const long sVE = (long)3 * S_LEN * VDIM;     // veff2 per-head stride

    cudaStreamWaitEvent(s0, e_kl, 0);
    // scores group 0 (heads 0..63):  K = 576
    gemm<0,1,0>(s0, p_qsA, p_ksB, p_scores,
                S_LEN, S_LEN, SKW,
                SKW, S_LEN, S_LEN,
                sQS, sKS, sSC, HG, SCALE, 0);
    cudaEventRecord(e_sc0, s0);
    // scores group 1 (heads 64..127)
    gemm<0,1,0>(s0, p_qsA + HG * sQS, p_ksB + HG * sKS, p_scores + HG * sSC,
                S_LEN, S_LEN, SKW,
                SKW, S_LEN, S_LEN,
                sQS, sKS, sSC, HG, SCALE, 0);

    // s2: softmax + PV for group 0 (overlaps scores group 1)
    cudaStreamWaitEvent(s2, e_sc0, 0);
    {
        dim3 grid(S_LEN, HG);
        softmax_probs2_k<<<grid, 256, 0, s2>>>(p_scores, p_probs2);
    }
    gemm<1,0,1>(s2, p_probs2, p_veff2, p_bigo2,
                S_LEN, VDIM, 3 * S_LEN,
                3 * S_LEN, VDIM, 3 * OUTW,
                sPR, sVE, (long)VDIM, HG, 1.f, OUTW);
    cudaEventRecord(e_pv0, s2);

    // s0: softmax + PV for group 1 (needs veff2/ow2 -> e2)
    cudaStreamWaitEvent(s0, e2, 0);
    {
        dim3 grid(S_LEN, HG);
        softmax_probs2_k<<<grid, 256, 0, s0>>>(p_scores + HG * sSC, p_probs2 + HG * sPR);
    }
    gemm<1,0,1>(s0, p_probs2 + HG * sPR, p_veff2 + HG * sVE, p_bigo2 + (long)HG * VDIM,
                S_LEN, VDIM, 3 * S_LEN,
                3 * S_LEN, VDIM, 3 * OUTW,
                sPR, sVE, (long)VDIM, HG, 1.f, OUTW);
    cudaEventRecord(e_pv1, s0);

    // ---- out GEMM, split-K across both streams ----
    const int KH = (3 * OUTW) / 2;               // 24576
    float* P1 = p_scores;                        // reuse (group-0 scores dead after softmax g0)
    float* P2 = p_q;                             // reuse (dead after convAoff/rope)
    cudaStreamWaitEvent(s0, e_pv0, 0);
    gemm<0,0,0>(s0, p_bigo2, p_ow2, P1, S_LEN, D_MODEL, KH,
                3 * OUTW, D_MODEL, D_MODEL, 0, 0, 0, 1, 1.f, 0);
    cudaStreamWaitEvent(s2, e_pv1, 0);
    gemm<0,0,0>(s2, p_bigo2 + KH, p_ow2 + (long)KH * D_MODEL, P2, S_LEN, D_MODEL, KH,
                3 * OUTW, D_MODEL, D_MODEL, 0, 0, 0, 1, 1.f, 0);
    cudaEventRecord(e_P2, s2);
    cudaStreamWaitEvent(s0, e_P2, 0);
    {
        long n4 = (long)S_LEN * D_MODEL / 4;
        int blocks = (int)((n4 + 255) / 256);
        if (blocks > 2048) blocks = 2048;
        add2_k<<<blocks, 256, 0, s0>>>(P1, P2, out, n4);
    }
    // streams/events intentionally not destroyed (may be referenced by active capture)
}

// round 16
// speedup vs baseline: 1.7312x; 1.0703x over previous
#include <cuda_runtime.h>
#include <cuda_bf16.h>
#include <math.h>
#include <stdint.h>

// ---------------- problem constants ----------------
#define S_LEN   1024
#define D_MODEL 5120
#define H_HEADS 128
#define Q_LORA  1536
#define KV_LORA 512
#define ROPE_D  64
#define NOPE_D  128
#define VDIM    128
#define Q_HEAD  192
#define LATENT  576
#define QBN     24576
#define OUTW    16384
#define HG      64            // head group size for pipelined attention tail
#define SKW     576           // scores split-K width (3 * (NOPE + ROPE))

typedef __nv_bfloat16 bf16;

// ---------------- scratch (device globals; no allocation) ----------------
__device__ __align__(16) bf16 g_h2    [(size_t)S_LEN * 3 * D_MODEL];
__device__ __align__(16) bf16 g_qaw2  [(size_t)3 * D_MODEL * Q_LORA];
__device__ __align__(16) bf16 g_qa2   [(size_t)S_LEN * 3 * Q_LORA];
__device__ __align__(16) bf16 g_qbw2  [(size_t)3 * Q_LORA * QBN];
__device__ __align__(16) bf16 g_kcA   [(size_t)H_HEADS * NOPE_D * 3 * KV_LORA]; // A-split kc_w per head
__device__ __align__(16) bf16 g_kvaw2 [(size_t)3 * D_MODEL * LATENT];
__device__ __align__(16) bf16 g_lat2  [(size_t)S_LEN * 3 * KV_LORA];
__device__ __align__(16) bf16 g_latT2 [(size_t)3 * KV_LORA * S_LEN];            // B-split latent^T
__device__ __align__(16) bf16 g_vc2   [(size_t)H_HEADS * 3 * KV_LORA * VDIM];
__device__ __align__(16) bf16 g_qsA   [(size_t)H_HEADS * S_LEN * SKW];          // scores A operand
__device__ __align__(16) bf16 g_ksB   [(size_t)H_HEADS * SKW * S_LEN];          // scores B operand
__device__ __align__(16) bf16 g_veff2 [(size_t)H_HEADS * 3 * S_LEN * VDIM];
__device__ __align__(16) bf16 g_probs2[(size_t)H_HEADS * S_LEN * 3 * S_LEN];
__device__ __align__(16) bf16 g_bigo2 [(size_t)S_LEN * 3 * OUTW];
__device__ __align__(16) bf16 g_ow2   [(size_t)3 * OUTW * D_MODEL];
// fp32 intermediates
__device__ __align__(16) float g_qa   [(size_t)S_LEN * Q_LORA];
__device__ __align__(16) float g_q    [(size_t)S_LEN * QBN];      // reused as out-partial slabs 1,3,5
__device__ __align__(16) float g_kv   [(size_t)S_LEN * LATENT];
__device__ __align__(16) float g_kfull[(size_t)S_LEN * LATENT];
__device__ __align__(16) float g_scores[(size_t)H_HEADS * S_LEN * S_LEN]; // head 0-15 region reused as out-partial slabs 0,2,4

// ---------------- PTX helpers ----------------
__device__ __forceinline__ void cp_async16(uint32_t dst, const void* src, bool pred) {
    int sz = pred ? 16 : 0;
    asm volatile("cp.async.cg.shared.global [%0], [%1], 16, %2;\n"
                 :: "r"(dst), "l"(src), "r"(sz));
}
__device__ __forceinline__ void cp_commit() {
    asm volatile("cp.async.commit_group;\n" ::: "memory");
}
__device__ __forceinline__ void ldsm_x4(uint32_t* r, uint32_t addr) {
    asm volatile("ldmatrix.sync.aligned.m8n8.x4.shared.b16 {%0,%1,%2,%3}, [%4];\n"
                 : "=r"(r[0]), "=r"(r[1]), "=r"(r[2]), "=r"(r[3]) : "r"(addr));
}
__device__ __forceinline__ void ldsm_x4_t(uint32_t* r, uint32_t addr) {
    asm volatile("ldmatrix.sync.aligned.m8n8.x4.trans.shared.b16 {%0,%1,%2,%3}, [%4];\n"
                 : "=r"(r[0]), "=r"(r[1]), "=r"(r[2]), "=r"(r[3]) : "r"(addr));
}
__device__ __forceinline__ void mma_bf16(float* d, const uint32_t* a, const uint32_t* b) {
    asm volatile("mma.sync.aligned.m16n8k16.row.col.f32.bf16.bf16.f32 "
                 "{%0,%1,%2,%3},{%4,%5,%6,%7},{%8,%9},{%0,%1,%2,%3};\n"
                 : "+f"(d[0]), "+f"(d[1]), "+f"(d[2]), "+f"(d[3])
                 : "r"(a[0]), "r"(a[1]), "r"(a[2]), "r"(a[3]), "r"(b[0]), "r"(b[1]));
}

__device__ __forceinline__ void split_bf16(float x, bf16& hi, bf16& lo) {
    hi = __float2bfloat16(x);
    lo = __float2bfloat16(x - __bfloat162float(hi));
}

// ---------------- templated bf16 tensor-core GEMM: 128x128x64, 3-stage ----------------
#define BM 128
#define BN 128
#define BK 64
#define ASTR (BK + 8)
#define BSTR (BN + 8)
#define NSTG 3
#define A_STG (BM * ASTR)
#define B_STG (BK * BSTR)
#define SMEM_ELEMS (NSTG * (A_STG + B_STG))
#define SMEM_BYTES (SMEM_ELEMS * 2)

template<int EPI, int TRI, int KLIM>
__global__ void __launch_bounds__(256, 2) gemm_t(
    const bf16* __restrict__ A, const bf16* __restrict__ B, void* __restrict__ Cv,
    int M, int N, int K, int lda, int ldb, int ldc,
    long sA, long sB, long sC, float alpha, int off2)
{
    extern __shared__ bf16 smem[];
    bf16 (*As)[BM][ASTR] = (bf16(*)[BM][ASTR])smem;
    bf16 (*Bs)[BK][BSTR] = (bf16(*)[BK][BSTR])(smem + NSTG * A_STG);

    int tm, tn;
    if (TRI) {
        int x = blockIdx.x;
        int r = (int)((-1.f + sqrtf(1.f + 8.f * (float)x)) * 0.5f);
        while ((r + 1) * (r + 2) / 2 <= x) ++r;
        while (r * (r + 1) / 2 > x) --r;
        tm = r; tn = x - r * (r + 1) / 2;
    } else { tn = blockIdx.x; tm = blockIdx.y; }

    const int m0 = tm * BM;
    const int n0 = tn * BN;
    A += (long)blockIdx.z * sA;
    B += (long)blockIdx.z * sB;

    int Keff = K;
    if (KLIM) { int lim = 3 * (m0 + BM); Keff = (lim < K) ? lim : K; }

    const int tid  = threadIdx.x;
    const int lane = tid & 31;
    const int warp = tid >> 5;
    const int wm   = warp >> 1;
    const int wn   = warp & 1;

    float acc[2][8][4];
#pragma unroll
    for (int a = 0; a < 2; a++)
#pragma unroll
        for (int b = 0; b < 8; b++)
#pragma unroll
            for (int c = 0; c < 4; c++) acc[a][b][c] = 0.f;

    const int ktiles = Keff / BK;

    auto load_tiles = [&](int buf, int kt) {
#pragma unroll
        for (int i = 0; i < 4; i++) {
            int seg = tid + 256 * i;
            int r = seg >> 3, c = (seg & 7) * 8;
            uint32_t dst = (uint32_t)__cvta_generic_to_shared(&As[buf][r][c]);
            bool okm = (m0 + r) < M;
            const bf16* src = okm ? (A + (long)(m0 + r) * lda + kt + c) : A;
            cp_async16(dst, src, okm);
        }
#pragma unroll
        for (int i = 0; i < 4; i++) {
            int seg = tid + 256 * i;
            int r = seg >> 4, c = (seg & 15) * 8;
            uint32_t dst = (uint32_t)__cvta_generic_to_shared(&Bs[buf][r][c]);
            bool ok = (n0 + c) < N;
            const bf16* src = ok ? (B + (long)(kt + r) * ldb + n0 + c) : B;
            cp_async16(dst, src, ok);
        }
        cp_commit();
    };

    load_tiles(0, 0);
    if (ktiles > 1) load_tiles(1, BK);

    for (int t = 0; t < ktiles; t++) {
        const int buf = t % NSTG;
        if (t + 2 < ktiles) {
            load_tiles((t + 2) % NSTG, (t + 2) * BK);
            asm volatile("cp.async.wait_group 2;" ::: "memory");
        } else if (t + 1 < ktiles) {
            asm volatile("cp.async.wait_group 1;" ::: "memory");
        } else {
            asm volatile("cp.async.wait_group 0;" ::: "memory");
        }
        __syncthreads();

#pragma unroll
        for (int kk = 0; kk < 4; kk++) {
            uint32_t af[2][4];
#pragma unroll
            for (int mt = 0; mt < 2; mt++) {
                uint32_t addr = (uint32_t)__cvta_generic_to_shared(
                    &As[buf][wm * 32 + mt * 16 + (lane & 15)][kk * 16 + (lane >> 4) * 8]);
                ldsm_x4(af[mt], addr);
            }
            uint32_t bfr[4][4];
#pragma unroll
            for (int np = 0; np < 4; np++) {
                uint32_t addr = (uint32_t)__cvta_generic_to_shared(
                    &Bs[buf][kk * 16 + (lane & 15)][wn * 64 + np * 16 + (lane >> 4) * 8]);
                ldsm_x4_t(bfr[np], addr);
            }
#pragma unroll
            for (int mt = 0; mt < 2; mt++)
#pragma unroll
                for (int nt = 0; nt < 8; nt++)
                    mma_bf16(acc[mt][nt], af[mt], &bfr[nt >> 1][(nt & 1) * 2]);
        }
        __syncthreads();
    }

    // ---- epilogue ----
    const int r  = lane >> 2;
    const int c2 = (lane & 3) * 2;

    auto emit = [&](int m, int n, float v0, float v1) {
        if (m >= M) return;
        v0 *= alpha; v1 *= alpha;
        if (EPI == 0) {
            float* C = (float*)Cv + (long)blockIdx.z * sC;
            C[(long)m * ldc + n]     = v0;
            C[(long)m * ldc + n + 1] = v1;
        } else if (EPI == 1) {
            bf16* C = (bf16*)Cv + (long)blockIdx.z * sC;
            bf16 h0, l0, h1, l1;
            split_bf16(v0, h0, l0); split_bf16(v1, h1, l1);
            __nv_bfloat162 hi2 = __nv_bfloat162(h0, h1);
            __nv_bfloat162 lo2 = __nv_bfloat162(l0, l1);
            long base = (long)m * ldc + n;
            *(__nv_bfloat162*)&C[base] = hi2;
            *(__nv_bfloat162*)&C[base + off2] = hi2;
            *(__nv_bfloat162*)&C[base + 2 * (long)off2] = lo2;
        } else {
            bf16* C = (bf16*)Cv + (long)blockIdx.z * sC;
            bf16 h0, l0, h1, l1;
            split_bf16(v0, h0, l0); split_bf16(v1, h1, l1);
            __nv_bfloat162 hi2 = __nv_bfloat162(h0, h1);
            __nv_bfloat162 lo2 = __nv_bfloat162(l0, l1);
            *(__nv_bfloat162*)&C[(long)(3 * m)     * ldc + n] = hi2;
            *(__nv_bfloat162*)&C[(long)(3 * m + 1) * ldc + n] = lo2;
            *(__nv_bfloat162*)&C[(long)(3 * m + 2) * ldc + n] = hi2;
        }
    };

#pragma unroll
    for (int mt = 0; mt < 2; mt++) {
#pragma unroll
        for (int nt = 0; nt < 8; nt++) {
            int m = m0 + wm * 32 + mt * 16 + r;
            int n = n0 + wn * 64 + nt * 8 + c2;
            if (n < N) {
                emit(m,     n, acc[mt][nt][0], acc[mt][nt][1]);
                emit(m + 8, n, acc[mt][nt][2], acc[mt][nt][3]);
            }
        }
    }
}

// ---------------- vectorized converters ----------------
union BV4 { bf16 b[4]; uint2 u; };

__global__ void convA4_k(const float* __restrict__ src, bf16* __restrict__ dst,
                         int M, int K, int lda, long ssrc)
{
    src += (long)blockIdx.z * ssrc;
    dst += (long)blockIdx.z * M * 3 * K;
    int K4 = K >> 2;
    long total = (long)M * K4;
    for (long idx = (long)blockIdx.x * blockDim.x + threadIdx.x; idx < total;
         idx += (long)gridDim.x * blockDim.x) {
        int m = (int)(idx / K4), k = (int)(idx % K4) * 4;
        float4 x = *(const float4*)(src + (long)m * lda + k);
        BV4 hv, lv;
        split_bf16(x.x, hv.b[0], lv.b[0]);
        split_bf16(x.y, hv.b[1], lv.b[1]);
        split_bf16(x.z, hv.b[2], lv.b[2]);
        split_bf16(x.w, hv.b[3], lv.b[3]);
        bf16* row = dst + (long)m * 3 * K;
        *(uint2*)&row[k]         = hv.u;
        *(uint2*)&row[K + k]     = hv.u;
        *(uint2*)&row[2 * K + k] = lv.u;
    }
}

__global__ void convAoff_k(const float* __restrict__ src, bf16* __restrict__ dst,
                           int M, int K, int lda, long ssrc, long sdst,
                           int rstride, int oh2, int olo)
{
    src += (long)blockIdx.z * ssrc;
    dst += (long)blockIdx.z * sdst;
    int K4 = K >> 2;
    long total = (long)M * K4;
    for (long idx = (long)blockIdx.x * blockDim.x + threadIdx.x; idx < total;
         idx += (long)gridDim.x * blockDim.x) {
        int m = (int)(idx / K4), k = (int)(idx % K4) * 4;
        float4 x = *(const float4*)(src + (long)m * lda + k);
        BV4 hv, lv;
        split_bf16(x.x, hv.b[0], lv.b[0]);
        split_bf16(x.y, hv.b[1], lv.b[1]);
        split_bf16(x.z, hv.b[2], lv.b[2]);
        split_bf16(x.w, hv.b[3], lv.b[3]);
        bf16* row = dst + (long)m * rstride;
        *(uint2*)&row[k]       = hv.u;
        *(uint2*)&row[oh2 + k] = hv.u;
        *(uint2*)&row[olo + k] = lv.u;
    }
}

__global__ void convB4_k(const float* __restrict__ src, bf16* __restrict__ dst,
                         int K, int N, int ldb, long ssrc)
{
    src += (long)blockIdx.z * ssrc;
    dst += (long)blockIdx.z * 3 * K * N;
    int N4 = N >> 2;
    long total = (long)K * N4;
    for (long idx = (long)blockIdx.x * blockDim.x + threadIdx.x; idx < total;
         idx += (long)gridDim.x * blockDim.x) {
        int k = (int)(idx / N4), n = (int)(idx % N4) * 4;
        float4 x = *(const float4*)(src + (long)k * ldb + n);
        BV4 hv, lv;
        split_bf16(x.x, hv.b[0], lv.b[0]);
        split_bf16(x.y, hv.b[1], lv.b[1]);
        split_bf16(x.z, hv.b[2], lv.b[2]);
        split_bf16(x.w, hv.b[3], lv.b[3]);
        *(uint2*)&dst[(long)k * N + n]           = hv.u;
        *(uint2*)&dst[((long)K + k) * N + n]     = lv.u;
        *(uint2*)&dst[((long)2 * K + k) * N + n] = hv.u;
    }
}

__global__ void convBt_k(const float* __restrict__ src, bf16* __restrict__ dst,
                         int K, int N, int lds)
{
    long total = (long)K * N;
    for (long idx = (long)blockIdx.x * blockDim.x + threadIdx.x; idx < total;
         idx += (long)gridDim.x * blockDim.x) {
        int k = (int)(idx / N), n = (int)(idx % N);
        float x = src[(long)n * lds + k];
        bf16 hi, lo; split_bf16(x, hi, lo);
        dst[(long)k * N + n] = hi;
        dst[((long)K + k) * N + n] = lo;
        dst[((long)2 * K + k) * N + n] = hi;
    }
}

__global__ void convKpe_k(const float* __restrict__ kfull, bf16* __restrict__ ksB)
{
    int k = blockIdx.x;   // 0..63
    int h = blockIdx.y;   // 0..127
    bf16* base = ksB + (size_t)h * SKW * S_LEN;
    for (int n = threadIdx.x; n < S_LEN; n += blockDim.x) {
        float v = kfull[(long)n * LATENT + KV_LORA + k];
        bf16 hi, lo; split_bf16(v, hi, lo);
        base[(long)(128 + k) * S_LEN + n] = hi;
        base[(long)(320 + k) * S_LEN + n] = hi;
        base[(long)(512 + k) * S_LEN + n] = lo;
    }
}

// ---------------- elementwise kernels ----------------
__global__ void add6_k(const float* __restrict__ a0, const float* __restrict__ a1,
                       const float* __restrict__ a2, const float* __restrict__ b0,
                       const float* __restrict__ b1, const float* __restrict__ b2,
                       float* __restrict__ c, long n4)
{
    for (long i = (long)blockIdx.x * blockDim.x + threadIdx.x; i < n4;
         i += (long)gridDim.x * blockDim.x) {
        float4 x0 = ((const float4*)a0)[i];
        float4 x1 = ((const float4*)a1)[i];
        float4 x2 = ((const float4*)a2)[i];
        float4 y0 = ((const float4*)b0)[i];
        float4 y1 = ((const float4*)b1)[i];
        float4 y2 = ((const float4*)b2)[i];
        float4 z;
        z.x = (x0.x + x1.x) + (x2.x + y0.x) + (y1.x + y2.x);
        z.y = (x0.y + x1.y) + (x2.y + y0.y) + (y1.y + y2.y);
        z.z = (x0.z + x1.z) + (x2.z + y0.z) + (y1.z + y2.z);
        z.w = (x0.w + x1.w) + (x2.w + y0.w) + (y1.w + y2.w);
        ((float4*)c)[i] = z;
    }
}

__global__ void rmsnorm_rows_k(float* x, const float* __restrict__ w, int W)
{
    int row = blockIdx.x;
    float* p = x + (long)row * W;
    __shared__ float red[256];
    int tid = threadIdx.x;
    float ss = 0.f;
    for (int i = tid; i < W; i += 256) { float v = p[i]; ss += v * v; }
    red[tid] = ss; __syncthreads();
    for (int st = 128; st > 0; st >>= 1) {
        if (tid < st) red[tid] += red[tid + st];
        __syncthreads();
    }
    float r = rsqrtf(red[0] / (float)W + 1e-6f);
    for (int i = tid; i < W; i += 256) p[i] = p[i] * r * w[i];
}

__global__ void build_kfull_k(const float* __restrict__ kv, const float* __restrict__ lnw,
                              const float* __restrict__ cosb, const float* __restrict__ sinb,
                              float* __restrict__ kfull)
{
    int s = blockIdx.x;
    int tid = threadIdx.x;
    const float* row = kv + (long)s * LATENT;
    float* out = kfull + (long)s * LATENT;
    __shared__ float red[256];
    float ss = 0.f;
    for (int i = tid; i < KV_LORA; i += 256) { float v = row[i]; ss += v * v; }
    red[tid] = ss; __syncthreads();
    for (int st = 128; st > 0; st >>= 1) {
        if (tid < st) red[tid] += red[tid + st];
        __syncthreads();
    }
    float r = rsqrtf(red[0] / (float)KV_LORA + 1e-6f);
    for (int i = tid; i < KV_LORA; i += 256) out[i] = row[i] * r * lnw[i];
    if (tid < ROPE_D) {
        int j = tid;
        float x = row[KV_LORA + j];
        float rot = (j < 32) ? -row[KV_LORA + j + 32] : row[KV_LORA + j - 32];
        out[KV_LORA + j] = x * cosb[s * ROPE_D + j] + rot * sinb[s * ROPE_D + j];
    }
}

__global__ void rope_qpe3_k(const float* __restrict__ q,
                            const float* __restrict__ cosb, const float* __restrict__ sinb,
                            bf16* __restrict__ qsA)
{
    int s = blockIdx.x;
    int h = blockIdx.y;
    int j = threadIdx.x;
    const float* x = q + (long)s * QBN + h * Q_HEAD + NOPE_D;
    float v = x[j];
    float rot = (j < 32) ? -x[j + 32] : x[j - 32];
    float val = v * cosb[s * ROPE_D + j] + rot * sinb[s * ROPE_D + j];
    bf16 hi, lo; split_bf16(val, hi, lo);
    bf16* row = qsA + ((long)h * S_LEN + s) * SKW;
    row[128 + j] = hi;
    row[512 + j] = hi;
    row[320 + j] = lo;
}

__global__ void softmax_probs2_k(const float* __restrict__ scores, bf16* __restrict__ probs2)
{
    int q = blockIdx.x;
    int h = blockIdx.y;
    int tid = threadIdx.x;
    const float* row = scores + ((long)h * S_LEN + q) * S_LEN;
    bf16* orow = probs2 + ((long)h * S_LEN + q) * (3 * S_LEN);
    int n = q + 1;
    int imax = ((q >> 7) + 1) << 7;
    __shared__ float red[256];

    int i0 = tid * 4;
    bool act = i0 < imax;
    float a[4] = {0.f, 0.f, 0.f, 0.f};
    if (act) { float4 v = *(const float4*)(row + i0); a[0]=v.x; a[1]=v.y; a[2]=v.z; a[3]=v.w; }

    float mx = -3.4e38f;
#pragma unroll
    for (int j = 0; j < 4; j++)
        if (i0 + j < n) mx = fmaxf(mx, a[j]);
    red[tid] = mx; __syncthreads();
    for (int st = 128; st > 0; st >>= 1) {
        if (tid < st) red[tid] = fmaxf(red[tid], red[tid + st]);
        __syncthreads();
    }
    mx = red[0];
    __syncthreads();

    float sum = 0.f;
#pragma unroll
    for (int j = 0; j < 4; j++) {
        a[j] = (i0 + j < n) ? __expf(a[j] - mx) : 0.f;
        sum += a[j];
    }
    red[tid] = sum; __syncthreads();
    for (int st = 128; st > 0; st >>= 1) {
        if (tid < st) red[tid] += red[tid + st];
        __syncthreads();
    }
    float inv = 1.f / red[0];

    if (act) {
        __align__(8) bf16 buf[12];
#pragma unroll
        for (int j = 0; j < 4; j++) {
            float p = a[j] * inv;
            bf16 hi, lo; split_bf16(p, hi, lo);
            buf[3 * j + 0] = hi;
            buf[3 * j + 1] = hi;
            buf[3 * j + 2] = lo;
        }
        uint2* dst = (uint2*)(orow + 3 * i0);
        const uint2* sb = (const uint2*)buf;
        dst[0] = sb[0]; dst[1] = sb[1]; dst[2] = sb[2];
    }
}

// ---------------- host-side launchers (stream-aware) ----------------
template<int EPI, int TRI, int KLIM>
static void gemm(cudaStream_t st, const bf16* A, const bf16* B, void* C,
                 int M, int N, int K, int lda, int ldb, int ldc,
                 long sA, long sB, long sC, int batch, float alpha, int off2)
{
    cudaFuncSetAttribute(gemm_t<EPI, TRI, KLIM>,
                         cudaFuncAttributeMaxDynamicSharedMemorySize, SMEM_BYTES);
    dim3 grid;
    if (TRI) {
        int t = M / BM;
        grid = dim3(t * (t + 1) / 2, 1, batch);
    } else {
        grid = dim3((N + BN - 1) / BN, (M + BM - 1) / BM, batch);
    }
    gemm_t<EPI, TRI, KLIM><<<grid, 256, SMEM_BYTES, st>>>(A, B, C, M, N, K, lda, ldb, ldc,
                                                          sA, sB, sC, alpha, off2);
}
static void convA(cudaStream_t st, const float* src, bf16* dst,
                  int M, int K, int lda, long ssrc, int batch)
{
    long total = (long)M * (K >> 2);
    int blocks = (int)((total + 255) / 256);
    if (blocks > 2048) blocks = 2048;
    convA4_k<<<dim3(blocks, 1, batch), 256, 0, st>>>(src, dst, M, K, lda, ssrc);
}
static void convB(cudaStream_t st, const float* src, bf16* dst,
                  int K, int N, int ldb, long ssrc, int batch)
{
    long total = (long)K * (N >> 2);
    int blocks = (int)((total + 255) / 256);
    if (blocks > 2048) blocks = 2048;
    convB4_k<<<dim3(blocks, 1, batch), 256, 0, st>>>(src, dst, K, N, ldb, ssrc);
}

extern "C" void kernel_launch(void* const* d_in, const int* in_sizes, int n_in,
                              void* d_out, int out_size)
{
    const float* h      = (const float*)d_in[0];
    const float* cosb   = (const float*)d_in[1];
    const float* sinb   = (const float*)d_in[2];
    const float* q_a_w  = (const float*)d_in[3];
    const float* q_a_ln = (const float*)d_in[4];
    const float* q_b_w  = (const float*)d_in[5];
    const float* kv_a_w = (const float*)d_in[6];
    const float* kv_ln  = (const float*)d_in[7];
    const float* kc_w   = (const float*)d_in[8];
    const float* vc_w   = (const float*)d_in[9];
    const float* o_w    = (const float*)d_in[10];
    float* out = (float*)d_out;

    bf16 *p_h2, *p_qaw2, *p_qa2, *p_qbw2, *p_kcA, *p_kvaw2, *p_lat2, *p_latT2;
    bf16 *p_vc2, *p_qsA, *p_ksB, *p_veff2, *p_probs2, *p_bigo2, *p_ow2;
    float *p_qa, *p_q, *p_kv, *p_kfull, *p_scores;
    cudaGetSymbolAddress((void**)&p_h2,     g_h2);
    cudaGetSymbolAddress((void**)&p_qaw2,   g_qaw2);
    cudaGetSymbolAddress((void**)&p_qa2,    g_qa2);
    cudaGetSymbolAddress((void**)&p_qbw2,   g_qbw2);
    cudaGetSymbolAddress((void**)&p_kcA,    g_kcA);
    cudaGetSymbolAddress((void**)&p_kvaw2,  g_kvaw2);
    cudaGetSymbolAddress((void**)&p_lat2,   g_lat2);
    cudaGetSymbolAddress((void**)&p_latT2,  g_latT2);
    cudaGetSymbolAddress((void**)&p_vc2,    g_vc2);
    cudaGetSymbolAddress((void**)&p_qsA,    g_qsA);
    cudaGetSymbolAddress((void**)&p_ksB,    g_ksB);
    cudaGetSymbolAddress((void**)&p_veff2,  g_veff2);
    cudaGetSymbolAddress((void**)&p_probs2, g_probs2);
    cudaGetSymbolAddress((void**)&p_bigo2,  g_bigo2);
    cudaGetSymbolAddress((void**)&p_ow2,    g_ow2);
    cudaGetSymbolAddress((void**)&p_qa,     g_qa);
    cudaGetSymbolAddress((void**)&p_q,      g_q);
    cudaGetSymbolAddress((void**)&p_kv,     g_kv);
    cudaGetSymbolAddress((void**)&p_kfull,  g_kfull);
    cudaGetSymbolAddress((void**)&p_scores, g_scores);

    double mscale = 0.1 * log(40.0) + 1.0;
    const float SCALE = (float)(pow((double)Q_HEAD, -0.5) * mscale * mscale);

    cudaStream_t s0 = (cudaStream_t)0;
    cudaStream_t s2;
    cudaStreamCreateWithFlags(&s2, cudaStreamNonBlocking);
    cudaEvent_t e1, e2, e3, e_kl, e_sc0, e_pv1, e_o024;
    cudaEventCreateWithFlags(&e1,    cudaEventDisableTiming);
    cudaEventCreateWithFlags(&e2,    cudaEventDisableTiming);
    cudaEventCreateWithFlags(&e3,    cudaEventDisableTiming);
    cudaEventCreateWithFlags(&e_kl,  cudaEventDisableTiming);
    cudaEventCreateWithFlags(&e_sc0, cudaEventDisableTiming);
    cudaEventCreateWithFlags(&e_pv1, cudaEventDisableTiming);
    cudaEventCreateWithFlags(&e_o024, cudaEventDisableTiming);

    // ---- stream0: input conversion, then fork ----
    convA(s0, h, p_h2, S_LEN, D_MODEL, D_MODEL, 0, 1);
    cudaEventRecord(e1, s0);
    cudaStreamWaitEvent(s2, e1, 0);

    // ---- s2: weight converters + kv-path + KL + veff ----
    convB(s2, q_b_w, p_qbw2, Q_LORA, QBN, QBN, 0, 1);
    cudaEventRecord(e3, s2);                 // qbw2 ready for s0's q GEMM
    // kv GEMM early so it overlaps s0's underfilled qa GEMM
    convB(s2, kv_a_w, p_kvaw2, D_MODEL, LATENT, LATENT, 0, 1);
    gemm<0,0,0>(s2, p_h2, p_kvaw2, p_kv, S_LEN, LATENT, 3 * D_MODEL,
                3 * D_MODEL, LATENT, LATENT, 0, 0, 0, 1, 1.f, 0);
    convA(s2, kc_w, p_kcA, NOPE_D, KV_LORA, KV_LORA, (long)NOPE_D * KV_LORA, H_HEADS);
    build_kfull_k<<<S_LEN, 256, 0, s2>>>(p_kv, kv_ln, cosb, sinb, p_kfull);
    {
        int blocks = (int)(((long)KV_LORA * S_LEN + 255) / 256);
        if (blocks > 2048) blocks = 2048;
        convBt_k<<<blocks, 256, 0, s2>>>(p_kfull, p_latT2, KV_LORA, S_LEN, LATENT);
    }
    {
        dim3 grid(ROPE_D, H_HEADS);
        convKpe_k<<<grid, 256, 0, s2>>>(p_kfull, p_ksB);
    }
    // KL_h = kc_w[h] @ latent^T  (overlaps s0's q GEMM)
    gemm<1,0,0>(s2, p_kcA, p_latT2, p_ksB,
                NOPE_D, S_LEN, 3 * KV_LORA,
                3 * KV_LORA, S_LEN, S_LEN,
                (long)NOPE_D * 3 * KV_LORA, 0, (long)SKW * S_LEN,
                H_HEADS, 1.f, 192 * S_LEN);
    cudaEventRecord(e_kl, s2);
    convA(s2, p_kfull, p_lat2, S_LEN, KV_LORA, LATENT, 0, 1);
    convB(s2, vc_w, p_vc2, KV_LORA, VDIM, VDIM, (long)KV_LORA * VDIM, H_HEADS);
    gemm<2,0,0>(s2, p_lat2, p_vc2, p_veff2,
                S_LEN, VDIM, 3 * KV_LORA,
                3 * KV_LORA, VDIM, VDIM,
                0, (long)3 * KV_LORA * VDIM, (long)3 * S_LEN * VDIM,
                H_HEADS, 1.f, 0);
    convB(s2, o_w, p_ow2, OUTW, D_MODEL, D_MODEL, 0, 1);
    cudaEventRecord(e2, s2);

    // ---- stream0: q-path ----
    convB(s0, q_a_w, p_qaw2, D_MODEL, Q_LORA, Q_LORA, 0, 1);
    gemm<0,0,0>(s0, p_h2, p_qaw2, p_qa, S_LEN, Q_LORA, 3 * D_MODEL,
                3 * D_MODEL, Q_LORA, Q_LORA, 0, 0, 0, 1, 1.f, 0);
    rmsnorm_rows_k<<<S_LEN, 256, 0, s0>>>(p_qa, q_a_ln, Q_LORA);
    convA(s0, p_qa, p_qa2, S_LEN, Q_LORA, Q_LORA, 0, 1);
    cudaStreamWaitEvent(s0, e3, 0);
    gemm<0,0,0>(s0, p_qa2, p_qbw2, p_q, S_LEN, QBN, 3 * Q_LORA,
                3 * Q_LORA, QBN, QBN, 0, 0, 0, 1, 1.f, 0);
    {
        long total = (long)S_LEN * (NOPE_D >> 2);
        int blocks = (int)((total + 255) / 256);
        if (blocks > 2048) blocks = 2048;
        convAoff_k<<<dim3(blocks, 1, H_HEADS), 256, 0, s0>>>(
            p_q, p_qsA, S_LEN, NOPE_D, QBN, (long)Q_HEAD, (long)S_LEN * SKW,
            SKW, 384, 192);
    }
    {
        dim3 grid(S_LEN, H_HEADS);
        rope_qpe3_k<<<grid, 64, 0, s0>>>(p_q, cosb, sinb, p_qsA);
    }

    // ---- attention tail, pipelined over two head groups ----
    const long sQS = (long)S_LEN * SKW;
    const long sKS = (long)SKW * S_LEN;
    const long sSC = (long)S_LEN * S_LEN;
    const long sPR = (long)S_LEN * 3 * S_LEN;
    const long sVE = (long)3 * S_LEN * VDIM;

    cudaStreamWaitEvent(s0, e_kl, 0);
    // scores group 0 (heads 0..63)
    gemm<0,1,0>(s0, p_qsA, p_ksB, p_scores,
                S_LEN, S_LEN, SKW,
                SKW, S_LEN, S_LEN,
                sQS, sKS, sSC, HG, SCALE, 0);
    cudaEventRecord(e_sc0, s0);
    // scores group 1 (heads 64..127)
    gemm<0,1,0>(s0, p_qsA + HG * sQS, p_ksB + HG * sKS, p_scores + HG * sSC,
                S_LEN, S_LEN, SKW,
                SKW, S_LEN, S_LEN,
                sQS, sKS, sSC, HG, SCALE, 0);

    // s2: softmax + PV for group 0 (overlaps scores group 1 on s0)
    cudaStreamWaitEvent(s2, e_sc0, 0);
    {
        dim3 grid(S_LEN, HG);
        softmax_probs2_k<<<grid, 256, 0, s2>>>(p_scores, p_probs2);
    }
    gemm<1,0,1>(s2, p_probs2, p_veff2, p_bigo2,
                S_LEN, VDIM, 3 * S_LEN,
                3 * S_LEN, VDIM, 3 * OUTW,
                sPR, sVE, (long)VDIM, HG, 1.f, OUTW);

    // s0: softmax + PV for group 1 (needs veff2/ow2 -> e2)
    cudaStreamWaitEvent(s0, e2, 0);
    {
        dim3 grid(S_LEN, HG);
        softmax_probs2_k<<<grid, 256, 0, s0>>>(p_scores + HG * sSC, p_probs2 + HG * sPR);
    }
    gemm<1,0,1>(s0, p_probs2 + HG * sPR, p_veff2 + HG * sVE, p_bigo2 + (long)HG * VDIM,
                S_LEN, VDIM, 3 * S_LEN,
                3 * S_LEN, VDIM, 3 * OUTW,
                sPR, sVE, (long)VDIM, HG, 1.f, OUTW);
    cudaEventRecord(e_pv1, s0);

    // ---- out GEMM: 6 column-group partials of K=8192 ----
    // bigo column blocks: [0,8192)=g0 hi, [8192,16384)=g1 hi, [16384,24576)=g0 hi,
    // [24576,32768)=g1 hi, [32768,40960)=g0 lo, [40960,49152)=g1 lo
    const int KP = 8192;
    const long SLAB = (long)S_LEN * D_MODEL;   // 5.24M floats per partial
    // g0 partials (0,2,4) on s2 right after PV g0 (their bigo columns are complete)
    float* Pg0[3] = { p_scores, p_scores + SLAB, p_scores + 2 * SLAB };  // heads 0-15 scores: dead
    float* Pg1[3] = { p_q, p_q + SLAB, p_q + 2 * SLAB };                 // q: dead after rope
#pragma unroll
    for (int i = 0; i < 3; i++) {
        int kp = (2 * i) * KP;
        gemm<0,0,0>(s2, p_bigo2 + kp, p_ow2 + (long)kp * D_MODEL, Pg0[i],
                    S_LEN, D_MODEL, KP, 3 * OUTW, D_MODEL, D_MODEL, 0, 0, 0, 1, 1.f, 0);
    }
    cudaEventRecord(e_o024, s2);
    // g1 partials (1,3,5) on s0 after PV g1
#pragma unroll
    for (int i = 0; i < 3; i++) {
        int kp = (2 * i + 1) * KP;
        gemm<0,0,0>(s0, p_bigo2 + kp, p_ow2 + (long)kp * D_MODEL, Pg1[i],
                    S_LEN, D_MODEL, KP, 3 * OUTW, D_MODEL, D_MODEL, 0, 0, 0, 1, 1.f, 0);
    }
    // final sum
    cudaStreamWaitEvent(s0, e_o024, 0);
    {
        long n4 = (long)S_LEN * D_MODEL / 4;
        int blocks = (int)((n4 + 255) / 256);
        if (blocks > 2048) blocks = 2048;
        add6_k<<<blocks, 256, 0, s0>>>(Pg0[0], Pg0[1], Pg0[2],
                                       Pg1[0], Pg1[1], Pg1[2], out, n4);
    }
    // streams/events intentionally not destroyed (may be referenced by active capture)
}